// round 6
// baseline (speedup 1.0000x reference)
#include <cuda_runtime.h>
#include <cuda_bf16.h>

// ---------------------------------------------------------------------------
// Problem constants
// ---------------------------------------------------------------------------
#define LAYERS 6
#define SEQ    256
#define BATCH  32
#define NF     1024      // n_features
#define NH     16        // heads
#define HD     64        // head dim
#define PD     1024      // packed dim = NH*HD
#define FF     4096
#define ROWS   (SEQ*BATCH)     // 8192 token rows
#define EPSLN  1e-5f

// ---------------------------------------------------------------------------
// Scratch (device globals: allocation-free per harness rules)
// ---------------------------------------------------------------------------
__device__ float g_h   [(size_t)ROWS * NF];    // LN output        32 MB
__device__ float g_qkv [(size_t)ROWS * 3 * PD];// qkv              96 MB
__device__ float g_attn[(size_t)ROWS * PD];    // attn out         32 MB
__device__ float g_ff  [(size_t)ROWS * FF];    // ffn hidden      128 MB

// ---------------------------------------------------------------------------
// f32x2 helpers (Blackwell packed fp32 pipe; only reachable via PTX)
// ---------------------------------------------------------------------------
__device__ __forceinline__ unsigned long long pack2(float lo, float hi) {
    unsigned long long r;
    asm("mov.b64 %0, {%1, %2};" : "=l"(r) : "f"(lo), "f"(hi));
    return r;
}
__device__ __forceinline__ void unpack2(unsigned long long v, float& lo, float& hi) {
    asm("mov.b64 {%0, %1}, %2;" : "=f"(lo), "=f"(hi) : "l"(v));
}
__device__ __forceinline__ unsigned long long fma2(unsigned long long a,
                                                   unsigned long long b,
                                                   unsigned long long c) {
    unsigned long long d;
    asm("fma.rn.f32x2 %0, %1, %2, %3;" : "=l"(d) : "l"(a), "l"(b), "l"(c));
    return d;
}

// ---------------------------------------------------------------------------
// Copy kernel (src -> x) : pure kernel launch, graph-safe
// ---------------------------------------------------------------------------
__global__ __launch_bounds__(256) void copy_kernel(const float* __restrict__ src,
                                                   float* __restrict__ dst) {
    size_t i = (size_t)blockIdx.x * 256 + threadIdx.x;
    ((float4*)dst)[i] = ((const float4*)src)[i];
}

// ---------------------------------------------------------------------------
// LayerNorm over N=1024, one block per row, 256 threads x float4
// Safe in-place (y may equal x).
// ---------------------------------------------------------------------------
__global__ __launch_bounds__(256) void ln_kernel(const float* __restrict__ x,
                                                 const float* __restrict__ g,
                                                 const float* __restrict__ b,
                                                 float* __restrict__ y) {
    int row = blockIdx.x;
    int t   = threadIdx.x;
    const float4* xr = (const float4*)(x + (size_t)row * NF);
    float4 v = xr[t];

    __shared__ float red[8];

    // mean
    float s = v.x + v.y + v.z + v.w;
    #pragma unroll
    for (int o = 16; o; o >>= 1) s += __shfl_xor_sync(0xffffffffu, s, o);
    if ((t & 31) == 0) red[t >> 5] = s;
    __syncthreads();
    float tot = red[0] + red[1] + red[2] + red[3] + red[4] + red[5] + red[6] + red[7];
    float mean = tot * (1.0f / NF);
    __syncthreads();   // everyone done reading red[] before reuse

    // variance
    float dx = v.x - mean, dy = v.y - mean, dz = v.z - mean, dw = v.w - mean;
    float sq = dx * dx + dy * dy + dz * dz + dw * dw;
    #pragma unroll
    for (int o = 16; o; o >>= 1) sq += __shfl_xor_sync(0xffffffffu, sq, o);
    if ((t & 31) == 0) red[t >> 5] = sq;
    __syncthreads();
    float vtot = red[0] + red[1] + red[2] + red[3] + red[4] + red[5] + red[6] + red[7];
    float inv = rsqrtf(vtot * (1.0f / NF) + EPSLN);

    float4 gg = ((const float4*)g)[t];
    float4 bb = ((const float4*)b)[t];
    float4 out;
    out.x = dx * inv * gg.x + bb.x;
    out.y = dy * inv * gg.y + bb.y;
    out.z = dz * inv * gg.z + bb.z;
    out.w = dw * inv * gg.w + bb.w;
    ((float4*)(y + (size_t)row * NF))[t] = out;
}

// ---------------------------------------------------------------------------
// SGEMM: C[M,Nn] = A[M,K] @ W[Nn,K]^T (+bias) (+relu / +residual-in-place)
// 128x128x16 tiles, 256 threads, 8x8 per thread, f32x2 dual-rate FMA,
// double-buffered SMEM. All dims are multiples of tile sizes here.
// EPI: 0 = bias store, 1 = bias+relu store, 2 = C = C + acc + bias
// ---------------------------------------------------------------------------
#define BM 128
#define BN 128
#define BKK 16

template <int EPI>
__global__ __launch_bounds__(256, 2)
void sgemm_kernel(const float* __restrict__ A, const float* __restrict__ W,
                  const float* __restrict__ bias, float* __restrict__ C,
                  int M, int Nn, int K) {
    __shared__ __align__(16) float As[2][BKK][BM];
    __shared__ __align__(16) float Bs[2][BKK][BN];

    int tid = threadIdx.x;
    int bm = blockIdx.y * BM;
    int bn = blockIdx.x * BN;
    int tx = tid & 15;   // n-dir
    int ty = tid >> 4;   // m-dir

    int lr = tid >> 2;            // 0..63 (loader row)
    int lc = (tid & 3) << 2;      // 0,4,8,12 (loader col, float4)
    const float* Ap = A + (size_t)(bm + lr) * K + lc;
    const float* Wp = W + (size_t)(bn + lr) * K + lc;
    const size_t rstep = (size_t)64 * K;

    unsigned long long acc[8][4];
    #pragma unroll
    for (int i = 0; i < 8; i++)
        #pragma unroll
        for (int j = 0; j < 4; j++) acc[i][j] = 0ull;

    // prologue: tile 0
    {
        float4 a0 = *(const float4*)Ap;
        float4 a1 = *(const float4*)(Ap + rstep);
        float4 w0 = *(const float4*)Wp;
        float4 w1 = *(const float4*)(Wp + rstep);
        As[0][lc + 0][lr] = a0.x; As[0][lc + 1][lr] = a0.y;
        As[0][lc + 2][lr] = a0.z; As[0][lc + 3][lr] = a0.w;
        As[0][lc + 0][lr + 64] = a1.x; As[0][lc + 1][lr + 64] = a1.y;
        As[0][lc + 2][lr + 64] = a1.z; As[0][lc + 3][lr + 64] = a1.w;
        Bs[0][lc + 0][lr] = w0.x; Bs[0][lc + 1][lr] = w0.y;
        Bs[0][lc + 2][lr] = w0.z; Bs[0][lc + 3][lr] = w0.w;
        Bs[0][lc + 0][lr + 64] = w1.x; Bs[0][lc + 1][lr + 64] = w1.y;
        Bs[0][lc + 2][lr + 64] = w1.z; Bs[0][lc + 3][lr + 64] = w1.w;
    }
    __syncthreads();

    int nt = K / BKK;
    int buf = 0;
    for (int kt = 0; kt < nt; kt++) {
        float4 na0, na1, nw0, nw1;
        bool pref = (kt + 1 < nt);
        if (pref) {
            const float* Ap2 = Ap + (size_t)(kt + 1) * BKK;
            const float* Wp2 = Wp + (size_t)(kt + 1) * BKK;
            na0 = *(const float4*)Ap2;
            na1 = *(const float4*)(Ap2 + rstep);
            nw0 = *(const float4*)Wp2;
            nw1 = *(const float4*)(Wp2 + rstep);
        }
        #pragma unroll
        for (int k = 0; k < BKK; k++) {
            float4 af0 = *(const float4*)&As[buf][k][ty * 8];
            float4 af1 = *(const float4*)&As[buf][k][ty * 8 + 4];
            ulonglong2 b01 = *(const ulonglong2*)&Bs[buf][k][tx * 8];
            ulonglong2 b23 = *(const ulonglong2*)&Bs[buf][k][tx * 8 + 4];
            unsigned long long bb0 = b01.x, bb1 = b01.y, bb2 = b23.x, bb3 = b23.y;
            float av[8] = {af0.x, af0.y, af0.z, af0.w, af1.x, af1.y, af1.z, af1.w};
            #pragma unroll
            for (int i = 0; i < 8; i++) {
                unsigned long long a2 = pack2(av[i], av[i]);
                acc[i][0] = fma2(a2, bb0, acc[i][0]);
                acc[i][1] = fma2(a2, bb1, acc[i][1]);
                acc[i][2] = fma2(a2, bb2, acc[i][2]);
                acc[i][3] = fma2(a2, bb3, acc[i][3]);
            }
        }
        if (pref) {
            int nb = buf ^ 1;
            As[nb][lc + 0][lr] = na0.x; As[nb][lc + 1][lr] = na0.y;
            As[nb][lc + 2][lr] = na0.z; As[nb][lc + 3][lr] = na0.w;
            As[nb][lc + 0][lr + 64] = na1.x; As[nb][lc + 1][lr + 64] = na1.y;
            As[nb][lc + 2][lr + 64] = na1.z; As[nb][lc + 3][lr + 64] = na1.w;
            Bs[nb][lc + 0][lr] = nw0.x; Bs[nb][lc + 1][lr] = nw0.y;
            Bs[nb][lc + 2][lr] = nw0.z; Bs[nb][lc + 3][lr] = nw0.w;
            Bs[nb][lc + 0][lr + 64] = nw1.x; Bs[nb][lc + 1][lr + 64] = nw1.y;
            Bs[nb][lc + 2][lr + 64] = nw1.z; Bs[nb][lc + 3][lr + 64] = nw1.w;
            __syncthreads();
            buf = nb;
        }
    }

    // epilogue
    const float* bp = bias + bn + tx * 8;
    float4 bv0 = *(const float4*)bp;
    float4 bv1 = *(const float4*)(bp + 4);
    float bvals[8] = {bv0.x, bv0.y, bv0.z, bv0.w, bv1.x, bv1.y, bv1.z, bv1.w};

    #pragma unroll
    for (int i = 0; i < 8; i++) {
        int m = bm + ty * 8 + i;
        float* crow = C + (size_t)m * Nn + bn + tx * 8;
        float o[8];
        #pragma unroll
        for (int j = 0; j < 4; j++) unpack2(acc[i][j], o[2 * j], o[2 * j + 1]);
        #pragma unroll
        for (int j = 0; j < 8; j++) o[j] += bvals[j];
        if (EPI == 1) {
            #pragma unroll
            for (int j = 0; j < 8; j++) o[j] = fmaxf(o[j], 0.0f);
        }
        if (EPI == 2) {
            float4 c0 = *(const float4*)crow;
            float4 c1 = *(const float4*)(crow + 4);
            o[0] += c0.x; o[1] += c0.y; o[2] += c0.z; o[3] += c0.w;
            o[4] += c1.x; o[5] += c1.y; o[6] += c1.z; o[7] += c1.w;
        }
        float4 s0 = {o[0], o[1], o[2], o[3]};
        float4 s1 = {o[4], o[5], o[6], o[7]};
        *(float4*)crow = s0;
        *(float4*)(crow + 4) = s1;
    }
}

// ---------------------------------------------------------------------------
// Fused attention: one CTA per (b,h). K,V resident in SMEM, per-warp softmax.
// qkv layout: [t, b, 3*PD] with q|k|v contiguous, head h at offset h*HD.
// out: [t, b, PD].
// ---------------------------------------------------------------------------
#define KST 68   // padded K row stride (floats): conflict-free LDS.128
#define ATTN_SMEM ((SEQ*KST + SEQ*HD + 8*4*SEQ) * 4)

__global__ __launch_bounds__(256) void attn_kernel(const float* __restrict__ qkv,
                                                   const float* __restrict__ mask,
                                                   float* __restrict__ out) {
    extern __shared__ __align__(16) float sm[];
    float* Ks = sm;                       // [256][68]
    float* Vs = Ks + SEQ * KST;           // [256][64]
    float* Ps = Vs + SEQ * HD;            // [8 warps][4 q][256]

    int bh = blockIdx.x;
    int b  = bh >> 4;
    int h  = bh & 15;
    int tid = threadIdx.x;

    // load K,V for this (b,h): 256 rows x 64 floats each
    for (int idx = tid; idx < SEQ * 16; idx += 256) {
        int s = idx >> 4;
        int c = (idx & 15) << 2;
        size_t base = ((size_t)s * BATCH + b) * (3 * PD) + (size_t)h * HD + c;
        float4 k4 = *(const float4*)(qkv + base + PD);
        float4 v4 = *(const float4*)(qkv + base + 2 * PD);
        *(float4*)(Ks + s * KST + c) = k4;
        *(float4*)(Vs + s * HD + c) = v4;
    }
    __syncthreads();

    int warp = tid >> 5, lane = tid & 31;
    float* Pw = Ps + warp * 4 * SEQ;
    const size_t qtstep = (size_t)BATCH * 3 * PD;   // stride between t rows

    for (int it = 0; it < 8; it++) {
        int t0 = warp * 32 + it * 4;
        const float* qp0 = qkv + ((size_t)t0 * BATCH + b) * (3 * PD) + (size_t)h * HD;

        // ---- scores: 4 queries x 256 keys, f32x2 over head-dim pairs ----
        unsigned long long sc2[4][8];
        #pragma unroll
        for (int q = 0; q < 4; q++)
            #pragma unroll
            for (int j = 0; j < 8; j++) sc2[q][j] = 0ull;

        #pragma unroll 2
        for (int d4 = 0; d4 < 16; d4++) {
            const float* qb = qp0 + 4 * d4;
            ulonglong2 aq0 = *(const ulonglong2*)(qb);
            ulonglong2 aq1 = *(const ulonglong2*)(qb + qtstep);
            ulonglong2 aq2 = *(const ulonglong2*)(qb + 2 * qtstep);
            ulonglong2 aq3 = *(const ulonglong2*)(qb + 3 * qtstep);
            #pragma unroll
            for (int j = 0; j < 8; j++) {
                int s = lane + 32 * j;
                ulonglong2 k2 = *(const ulonglong2*)(Ks + s * KST + 4 * d4);
                sc2[0][j] = fma2(aq0.x, k2.x, sc2[0][j]);
                sc2[0][j] = fma2(aq0.y, k2.y, sc2[0][j]);
                sc2[1][j] = fma2(aq1.x, k2.x, sc2[1][j]);
                sc2[1][j] = fma2(aq1.y, k2.y, sc2[1][j]);
                sc2[2][j] = fma2(aq2.x, k2.x, sc2[2][j]);
                sc2[2][j] = fma2(aq2.y, k2.y, sc2[2][j]);
                sc2[3][j] = fma2(aq3.x, k2.x, sc2[3][j]);
                sc2[3][j] = fma2(aq3.y, k2.y, sc2[3][j]);
            }
        }

        // ---- softmax per query row ----
        #pragma unroll
        for (int q = 0; q < 4; q++) {
            float pr[8];
            const float* mrow = mask + (size_t)(t0 + q) * SEQ;
            #pragma unroll
            for (int j = 0; j < 8; j++) {
                float lo, hi;
                unpack2(sc2[q][j], lo, hi);
                pr[j] = (lo + hi) * 0.125f + mrow[lane + 32 * j];
            }
            float mx = pr[0];
            #pragma unroll
            for (int j = 1; j < 8; j++) mx = fmaxf(mx, pr[j]);
            #pragma unroll
            for (int o = 16; o; o >>= 1) mx = fmaxf(mx, __shfl_xor_sync(0xffffffffu, mx, o));
            float sum = 0.0f;
            #pragma unroll
            for (int j = 0; j < 8; j++) { pr[j] = __expf(pr[j] - mx); sum += pr[j]; }
            #pragma unroll
            for (int o = 16; o; o >>= 1) sum += __shfl_xor_sync(0xffffffffu, sum, o);
            float inv = 1.0f / sum;
            #pragma unroll
            for (int j = 0; j < 8; j++) Pw[q * SEQ + lane + 32 * j] = pr[j] * inv;
        }
        __syncwarp();

        // ---- o = P @ V : each lane owns 2 head dims, 4 queries share V loads ----
        float2 acc0 = {0, 0}, acc1 = {0, 0}, acc2v = {0, 0}, acc3 = {0, 0};
        const float* vcol = Vs + 2 * lane;
        for (int s = 0; s < SEQ; s++) {
            float2 v2 = *(const float2*)(vcol + s * HD);
            float p0 = Pw[s];
            float p1 = Pw[SEQ + s];
            float p2 = Pw[2 * SEQ + s];
            float p3 = Pw[3 * SEQ + s];
            acc0.x = fmaf(p0, v2.x, acc0.x); acc0.y = fmaf(p0, v2.y, acc0.y);
            acc1.x = fmaf(p1, v2.x, acc1.x); acc1.y = fmaf(p1, v2.y, acc1.y);
            acc2v.x = fmaf(p2, v2.x, acc2v.x); acc2v.y = fmaf(p2, v2.y, acc2v.y);
            acc3.x = fmaf(p3, v2.x, acc3.x); acc3.y = fmaf(p3, v2.y, acc3.y);
        }
        size_t obase = ((size_t)t0 * BATCH + b) * PD + (size_t)h * HD + 2 * lane;
        size_t ostep = (size_t)BATCH * PD;
        *(float2*)(out + obase)             = acc0;
        *(float2*)(out + obase + ostep)     = acc1;
        *(float2*)(out + obase + 2 * ostep) = acc2v;
        *(float2*)(out + obase + 3 * ostep) = acc3;
        __syncwarp();
    }
}

// ---------------------------------------------------------------------------
// Host orchestration
// ---------------------------------------------------------------------------
extern "C" void kernel_launch(void* const* d_in, const int* in_sizes, int n_in,
                              void* d_out, int out_size) {
    const float* src  = (const float*)d_in[0];
    const float* mask = (const float*)d_in[1];
    const float* Wqkv = (const float*)d_in[2];
    const float* bqkv = (const float*)d_in[3];
    const float* Wo   = (const float*)d_in[4];
    const float* bo   = (const float*)d_in[5];
    const float* ln1g = (const float*)d_in[6];
    const float* ln1b = (const float*)d_in[7];
    const float* ln2g = (const float*)d_in[8];
    const float* ln2b = (const float*)d_in[9];
    const float* W1   = (const float*)d_in[10];
    const float* b1   = (const float*)d_in[11];
    const float* W2   = (const float*)d_in[12];
    const float* b2   = (const float*)d_in[13];
    const float* lnfg = (const float*)d_in[14];
    const float* lnfb = (const float*)d_in[15];

    float* x = (float*)d_out;

    void *ph, *pqkv, *pattn, *pff;
    cudaGetSymbolAddress(&ph, g_h);
    cudaGetSymbolAddress(&pqkv, g_qkv);
    cudaGetSymbolAddress(&pattn, g_attn);
    cudaGetSymbolAddress(&pff, g_ff);
    float* h  = (float*)ph;
    float* qk = (float*)pqkv;
    float* at = (float*)pattn;
    float* ff = (float*)pff;

    cudaFuncSetAttribute(attn_kernel, cudaFuncAttributeMaxDynamicSharedMemorySize,
                         ATTN_SMEM);

    // x = src
    copy_kernel<<<ROWS * NF / (256 * 4), 256>>>(src, x);

    dim3 gQKV(3 * PD / BN, ROWS / BM);   // (24, 64)
    dim3 gWO(NF / BN, ROWS / BM);        // (8, 64)
    dim3 gW1(FF / BN, ROWS / BM);        // (32, 64)
    dim3 gW2(NF / BN, ROWS / BM);        // (8, 64)

    for (int l = 0; l < LAYERS; l++) {
        const float* wqkv = Wqkv + (size_t)l * 3 * PD * NF;
        const float* bq   = bqkv + (size_t)l * 3 * PD;
        const float* wo   = Wo   + (size_t)l * NF * PD;
        const float* bo_  = bo   + (size_t)l * NF;
        const float* w1   = W1   + (size_t)l * FF * NF;
        const float* bb1  = b1   + (size_t)l * FF;
        const float* w2   = W2   + (size_t)l * NF * FF;
        const float* bb2  = b2   + (size_t)l * NF;

        // --- attention block ---
        ln_kernel<<<ROWS, 256>>>(x, ln1g + (size_t)l * NF, ln1b + (size_t)l * NF, h);
        sgemm_kernel<0><<<gQKV, 256>>>(h, wqkv, bq, qk, ROWS, 3 * PD, NF);
        attn_kernel<<<BATCH * NH, 256, ATTN_SMEM>>>(qk, mask, at);
        sgemm_kernel<2><<<gWO, 256>>>(at, wo, bo_, x, ROWS, NF, PD);   // x += ...

        // --- FFN block ---
        ln_kernel<<<ROWS, 256>>>(x, ln2g + (size_t)l * NF, ln2b + (size_t)l * NF, h);
        sgemm_kernel<1><<<gW1, 256>>>(h, w1, bb1, ff, ROWS, FF, NF);
        sgemm_kernel<2><<<gW2, 256>>>(ff, w2, bb2, x, ROWS, NF, FF);   // x += ...
    }

    // final LN (in-place on d_out)
    ln_kernel<<<ROWS, 256>>>(x, lnfg, lnfb, x);
}

// round 9
// speedup vs baseline: 2.3046x; 2.3046x over previous
#include <cuda_runtime.h>
#include <cuda_bf16.h>
#include <cstdint>

// ---------------------------------------------------------------------------
// Problem constants
// ---------------------------------------------------------------------------
#define LAYERS 6
#define SEQ    256
#define BATCH  32
#define NF     1024
#define NH     16
#define HD     64
#define PD     1024
#define FF     4096
#define ROWS   (SEQ*BATCH)     // 8192
#define EPSLN  1e-5f

// ---------------------------------------------------------------------------
// Scratch (device globals; allocation-free per harness rules)
// ---------------------------------------------------------------------------
__device__ float          g_qkv[(size_t)ROWS * 3 * PD];     // 96 MB fp32
__device__ __nv_bfloat16  g_ah [(size_t)ROWS * NF];         // activation hi
__device__ __nv_bfloat16  g_al [(size_t)ROWS * NF];         // activation lo
__device__ __nv_bfloat16  g_ffh[(size_t)ROWS * FF];
__device__ __nv_bfloat16  g_ffl[(size_t)ROWS * FF];
__device__ __nv_bfloat16  g_wh [(size_t)FF * NF];           // weight hi
__device__ __nv_bfloat16  g_wl [(size_t)FF * NF];           // weight lo

// ---------------------------------------------------------------------------
// PTX helpers (base sm_103 instruction set ONLY — no tcgen05 / no 'a' features)
// ---------------------------------------------------------------------------
__device__ __forceinline__ uint32_t smem_u32(const void* p) {
    uint32_t a;
    asm("{ .reg .u64 t; cvta.to.shared.u64 t, %1; cvt.u32.u64 %0, t; }"
        : "=r"(a) : "l"(p));
    return a;
}
__device__ __forceinline__ void cp_async16(uint32_t saddr, const void* gaddr) {
    asm volatile("cp.async.cg.shared.global [%0], [%1], 16;"
                 :: "r"(saddr), "l"(gaddr) : "memory");
}
__device__ __forceinline__ void cp_commit() {
    asm volatile("cp.async.commit_group;" ::: "memory");
}
template <int N>
__device__ __forceinline__ void cp_wait() {
    asm volatile("cp.async.wait_group %0;" :: "n"(N) : "memory");
}
__device__ __forceinline__ void ldsm_x4(uint32_t* r, uint32_t addr) {
    asm volatile("ldmatrix.sync.aligned.m8n8.x4.shared.b16 {%0,%1,%2,%3}, [%4];"
                 : "=r"(r[0]), "=r"(r[1]), "=r"(r[2]), "=r"(r[3]) : "r"(addr));
}
__device__ __forceinline__ void ldsm_x2(uint32_t* r, uint32_t addr) {
    asm volatile("ldmatrix.sync.aligned.m8n8.x2.shared.b16 {%0,%1}, [%2];"
                 : "=r"(r[0]), "=r"(r[1]) : "r"(addr));
}
__device__ __forceinline__ void mma16816(float* c, const uint32_t* a, const uint32_t* b) {
    asm volatile(
        "mma.sync.aligned.m16n8k16.row.col.f32.bf16.bf16.f32 "
        "{%0,%1,%2,%3}, {%4,%5,%6,%7}, {%8,%9}, {%0,%1,%2,%3};"
        : "+f"(c[0]), "+f"(c[1]), "+f"(c[2]), "+f"(c[3])
        : "r"(a[0]), "r"(a[1]), "r"(a[2]), "r"(a[3]), "r"(b[0]), "r"(b[1]));
}

// f32x2 helpers for attention (verified to compile on base sm_103 in R6)
__device__ __forceinline__ unsigned long long fma2(unsigned long long a,
                                                   unsigned long long b,
                                                   unsigned long long c) {
    unsigned long long d;
    asm("fma.rn.f32x2 %0, %1, %2, %3;" : "=l"(d) : "l"(a), "l"(b), "l"(c));
    return d;
}
__device__ __forceinline__ void unpack2(unsigned long long v, float& lo, float& hi) {
    asm("mov.b64 {%0, %1}, %2;" : "=f"(lo), "=f"(hi) : "l"(v));
}

// ---------------------------------------------------------------------------
// Utility kernels
// ---------------------------------------------------------------------------
__global__ __launch_bounds__(256) void copy_kernel(const float* __restrict__ src,
                                                   float* __restrict__ dst) {
    size_t i = (size_t)blockIdx.x * 256 + threadIdx.x;
    ((float4*)dst)[i] = ((const float4*)src)[i];
}

// fp32 -> bf16 hi/lo split (weights)
__global__ __launch_bounds__(256) void convw_kernel(const float* __restrict__ w,
                                                    __nv_bfloat16* __restrict__ hi,
                                                    __nv_bfloat16* __restrict__ lo) {
    size_t i = (size_t)blockIdx.x * 256 + threadIdx.x;
    float4 v = ((const float4*)w)[i];
    __nv_bfloat16 hx = __float2bfloat16_rn(v.x);
    __nv_bfloat16 hy = __float2bfloat16_rn(v.y);
    __nv_bfloat16 hz = __float2bfloat16_rn(v.z);
    __nv_bfloat16 hw = __float2bfloat16_rn(v.w);
    __nv_bfloat162 h0; h0.x = hx; h0.y = hy;
    __nv_bfloat162 h1; h1.x = hz; h1.y = hw;
    __nv_bfloat162 l0, l1;
    l0.x = __float2bfloat16_rn(v.x - __bfloat162float(hx));
    l0.y = __float2bfloat16_rn(v.y - __bfloat162float(hy));
    l1.x = __float2bfloat16_rn(v.z - __bfloat162float(hz));
    l1.y = __float2bfloat16_rn(v.w - __bfloat162float(hw));
    ((__nv_bfloat162*)hi)[2 * i]     = h0;
    ((__nv_bfloat162*)hi)[2 * i + 1] = h1;
    ((__nv_bfloat162*)lo)[2 * i]     = l0;
    ((__nv_bfloat162*)lo)[2 * i + 1] = l1;
}

// ---------------------------------------------------------------------------
// LayerNorm over N=1024. MODE 0: fp32 out. MODE 1: bf16 hi/lo out.
// ---------------------------------------------------------------------------
template <int MODE>
__global__ __launch_bounds__(256) void ln_kernel(const float* __restrict__ x,
                                                 const float* __restrict__ g,
                                                 const float* __restrict__ b,
                                                 float* __restrict__ y,
                                                 __nv_bfloat16* __restrict__ oh,
                                                 __nv_bfloat16* __restrict__ ol) {
    int row = blockIdx.x;
    int t   = threadIdx.x;
    const float4* xr = (const float4*)(x + (size_t)row * NF);
    float4 v = xr[t];

    __shared__ float red[8];
    float s = v.x + v.y + v.z + v.w;
    #pragma unroll
    for (int o = 16; o; o >>= 1) s += __shfl_xor_sync(0xffffffffu, s, o);
    if ((t & 31) == 0) red[t >> 5] = s;
    __syncthreads();
    float tot = red[0] + red[1] + red[2] + red[3] + red[4] + red[5] + red[6] + red[7];
    float mean = tot * (1.0f / NF);
    __syncthreads();

    float dx = v.x - mean, dy = v.y - mean, dz = v.z - mean, dw = v.w - mean;
    float sq = dx * dx + dy * dy + dz * dz + dw * dw;
    #pragma unroll
    for (int o = 16; o; o >>= 1) sq += __shfl_xor_sync(0xffffffffu, sq, o);
    if ((t & 31) == 0) red[t >> 5] = sq;
    __syncthreads();
    float vtot = red[0] + red[1] + red[2] + red[3] + red[4] + red[5] + red[6] + red[7];
    float inv = rsqrtf(vtot * (1.0f / NF) + EPSLN);

    float4 gg = ((const float4*)g)[t];
    float4 bb = ((const float4*)b)[t];
    float4 out;
    out.x = dx * inv * gg.x + bb.x;
    out.y = dy * inv * gg.y + bb.y;
    out.z = dz * inv * gg.z + bb.z;
    out.w = dw * inv * gg.w + bb.w;

    if (MODE == 0) {
        ((float4*)(y + (size_t)row * NF))[t] = out;
    } else {
        size_t base = (size_t)row * NF + (size_t)t * 4;
        __nv_bfloat16 hx = __float2bfloat16_rn(out.x);
        __nv_bfloat16 hy = __float2bfloat16_rn(out.y);
        __nv_bfloat16 hz = __float2bfloat16_rn(out.z);
        __nv_bfloat16 hw = __float2bfloat16_rn(out.w);
        __nv_bfloat162 h0; h0.x = hx; h0.y = hy;
        __nv_bfloat162 h1; h1.x = hz; h1.y = hw;
        __nv_bfloat162 l0, l1;
        l0.x = __float2bfloat16_rn(out.x - __bfloat162float(hx));
        l0.y = __float2bfloat16_rn(out.y - __bfloat162float(hy));
        l1.x = __float2bfloat16_rn(out.z - __bfloat162float(hz));
        l1.y = __float2bfloat16_rn(out.w - __bfloat162float(hw));
        *(__nv_bfloat162*)(oh + base)     = h0;
        *(__nv_bfloat162*)(oh + base + 2) = h1;
        *(__nv_bfloat162*)(ol + base)     = l0;
        *(__nv_bfloat162*)(ol + base + 2) = l1;
    }
}

// ---------------------------------------------------------------------------
// HMMA GEMM: C[M,Nn] = (Ah+Al)[M,K] @ (Wh+Wl)[Nn,K]^T (+bias)(+epilogue)
// via mma.sync m16n8k16 bf16, products AhWh + AhWl + AlWh.
// CTA tile 128x128, 8 warps (2x4), warp tile 64x32, K-chunk 64,
// cp.async double-buffered SMEM, +8-elem row pad for conflict-free ldmatrix.
// EPI 0: bias, fp32 store. EPI 1: bias+relu -> bf16 hi/lo. EPI 2: C += acc+bias.
// ---------------------------------------------------------------------------
#define KC   64
#define AST  72                       // padded row length in bf16 elems
#define ARB  (AST*2)                  // 144 bytes per row
#define TILEB (128*ARB)               // 18432 bytes per array tile
#define STAGEB (4*TILEB)              // 73728 per stage (Ah|Al|Wh|Wl)
#define GEMM_SMEM (2*STAGEB)          // 147456

__device__ __forceinline__ void gemm_issue_chunk(
    const __nv_bfloat16* pAh, const __nv_bfloat16* pAl,
    const __nv_bfloat16* pWh, const __nv_bfloat16* pWl,
    int K, int c, uint32_t dst0, int tid) {
    const __nv_bfloat16* srcs[4] = {pAh + (size_t)c * KC, pAl + (size_t)c * KC,
                                    pWh + (size_t)c * KC, pWl + (size_t)c * KC};
    #pragma unroll
    for (int arr = 0; arr < 4; arr++) {
        const __nv_bfloat16* p = srcs[arr];
        uint32_t d0 = dst0 + arr * TILEB;
        #pragma unroll
        for (int i = 0; i < 4; i++) {
            int idx = i * 256 + tid;
            int r = idx >> 3, cc = idx & 7;
            cp_async16(d0 + r * ARB + cc * 16, p + (size_t)r * K + cc * 8);
        }
    }
    cp_commit();
}

template <int EPI>
__global__ __launch_bounds__(256, 1)
void tc_gemm(const __nv_bfloat16* __restrict__ Ah, const __nv_bfloat16* __restrict__ Al,
             const __nv_bfloat16* __restrict__ Wh, const __nv_bfloat16* __restrict__ Wl,
             const float* __restrict__ bias, float* __restrict__ C,
             __nv_bfloat16* __restrict__ Oh, __nv_bfloat16* __restrict__ Ol,
             int Nn, int K) {
    extern __shared__ __align__(16) char smem[];
    __shared__ float sbias[128];
    uint32_t sb = smem_u32(smem);
    int tid = threadIdx.x;
    int bm = blockIdx.y * 128;
    int bn = blockIdx.x * 128;

    if (tid < 128) sbias[tid] = bias[bn + tid];

    const __nv_bfloat16* pAh = Ah + (size_t)bm * K;
    const __nv_bfloat16* pAl = Al + (size_t)bm * K;
    const __nv_bfloat16* pWh = Wh + (size_t)bn * K;
    const __nv_bfloat16* pWl = Wl + (size_t)bn * K;

    int l = tid & 31, warp = tid >> 5;
    int wm = warp >> 2, wn = warp & 3;

    float acc[4][4][4];
    #pragma unroll
    for (int i = 0; i < 4; i++)
        #pragma unroll
        for (int j = 0; j < 4; j++)
            #pragma unroll
            for (int k = 0; k < 4; k++) acc[i][j][k] = 0.0f;

    // ldmatrix lane addressing (byte offsets within a tile)
    int arow = wm * 64 + (l & 15);           // + i*16
    int acolb = ((l >> 4) * 8) * 2;          // + ks*32 bytes
    int brow = wn * 32 + (l & 7);            // + j*8
    int bcolb = (((l >> 3) & 1) * 8) * 2;    // + ks*32 bytes

    int NC = K / KC;
    gemm_issue_chunk(pAh, pAl, pWh, pWl, K, 0, sb, tid);

    for (int c = 0; c < NC; c++) {
        int stage = c & 1;
        if (c + 1 < NC) {
            gemm_issue_chunk(pAh, pAl, pWh, pWl, K, c + 1,
                             sb + ((c + 1) & 1) * STAGEB, tid);
            cp_wait<1>();
        } else {
            cp_wait<0>();
        }
        __syncthreads();

        uint32_t sA  = sb + stage * STAGEB;
        uint32_t sAl = sA + TILEB;
        uint32_t sW  = sA + 2 * TILEB;
        uint32_t sWl = sA + 3 * TILEB;

        #pragma unroll
        for (int ks = 0; ks < KC / 16; ks++) {
            uint32_t ah[4][4], al4[4][4], wh[4][2], wl4[4][2];
            #pragma unroll
            for (int i = 0; i < 4; i++) {
                uint32_t off = (uint32_t)(arow + i * 16) * ARB + ks * 32 + acolb;
                ldsm_x4(ah[i],  sA  + off);
                ldsm_x4(al4[i], sAl + off);
            }
            #pragma unroll
            for (int j = 0; j < 4; j++) {
                uint32_t off = (uint32_t)(brow + j * 8) * ARB + ks * 32 + bcolb;
                ldsm_x2(wh[j],  sW  + off);
                ldsm_x2(wl4[j], sWl + off);
            }
            #pragma unroll
            for (int i = 0; i < 4; i++)
                #pragma unroll
                for (int j = 0; j < 4; j++) {
                    mma16816(acc[i][j], ah[i],  wh[j]);
                    mma16816(acc[i][j], ah[i],  wl4[j]);
                    mma16816(acc[i][j], al4[i], wh[j]);
                }
        }
        __syncthreads();
    }

    // epilogue: C fragment: c0,c1 -> (row, col..col+1); c2,c3 -> (row+8, ..)
    int r0 = bm + wm * 64 + (l >> 2);
    int cb = wn * 32 + 2 * (l & 3);
    #pragma unroll
    for (int i = 0; i < 4; i++) {
        #pragma unroll
        for (int j = 0; j < 4; j++) {
            int col = cb + j * 8;
            float b0 = sbias[col], b1 = sbias[col + 1];
            #pragma unroll
            for (int half = 0; half < 2; half++) {
                int m = r0 + i * 16 + half * 8;
                float v0 = acc[i][j][2 * half]     + b0;
                float v1 = acc[i][j][2 * half + 1] + b1;
                size_t idx = (size_t)m * Nn + bn + col;
                if (EPI == 0) {
                    float2 s = {v0, v1};
                    *(float2*)(C + idx) = s;
                } else if (EPI == 2) {
                    float2 old = *(const float2*)(C + idx);
                    float2 s = {v0 + old.x, v1 + old.y};
                    *(float2*)(C + idx) = s;
                } else {  // EPI 1: relu -> bf16 hi/lo split
                    v0 = fmaxf(v0, 0.0f);
                    v1 = fmaxf(v1, 0.0f);
                    __nv_bfloat16 h0 = __float2bfloat16_rn(v0);
                    __nv_bfloat16 h1 = __float2bfloat16_rn(v1);
                    __nv_bfloat162 h2; h2.x = h0; h2.y = h1;
                    __nv_bfloat162 l2;
                    l2.x = __float2bfloat16_rn(v0 - __bfloat162float(h0));
                    l2.y = __float2bfloat16_rn(v1 - __bfloat162float(h1));
                    *(__nv_bfloat162*)(Oh + idx) = h2;
                    *(__nv_bfloat162*)(Ol + idx) = l2;
                }
            }
        }
    }
}

// ---------------------------------------------------------------------------
// Fused attention: one CTA per (b,h), 512 threads, K/V resident in SMEM.
// Reads qkv fp32, writes attention output as bf16 hi/lo split.
// ---------------------------------------------------------------------------
#define KST 68
#define ATTN_SMEM ((SEQ*KST + SEQ*HD + 16*4*SEQ) * 4)

__global__ __launch_bounds__(512, 1) void attn_kernel(const float* __restrict__ qkv,
                                                      const float* __restrict__ mask,
                                                      __nv_bfloat16* __restrict__ oh,
                                                      __nv_bfloat16* __restrict__ ol) {
    extern __shared__ __align__(16) float sm[];
    float* Ks = sm;                       // [256][68]
    float* Vs = Ks + SEQ * KST;           // [256][64]
    float* Ps = Vs + SEQ * HD;            // [16 warps][4 q][256]

    int bh = blockIdx.x;
    int b  = bh >> 4;
    int h  = bh & 15;
    int tid = threadIdx.x;

    for (int idx = tid; idx < SEQ * 16; idx += 512) {
        int s = idx >> 4;
        int c = (idx & 15) << 2;
        size_t base = ((size_t)s * BATCH + b) * (3 * PD) + (size_t)h * HD + c;
        float4 k4 = *(const float4*)(qkv + base + PD);
        float4 v4 = *(const float4*)(qkv + base + 2 * PD);
        *(float4*)(Ks + s * KST + c) = k4;
        *(float4*)(Vs + s * HD + c) = v4;
    }
    __syncthreads();

    int warp = tid >> 5, lane = tid & 31;
    float* Pw = Ps + warp * 4 * SEQ;
    const size_t qtstep = (size_t)BATCH * 3 * PD;

    for (int it = 0; it < 4; it++) {
        int t0 = warp * 16 + it * 4;
        const float* qp0 = qkv + ((size_t)t0 * BATCH + b) * (3 * PD) + (size_t)h * HD;

        unsigned long long sc2[4][8];
        #pragma unroll
        for (int q = 0; q < 4; q++)
            #pragma unroll
            for (int j = 0; j < 8; j++) sc2[q][j] = 0ull;

        #pragma unroll 2
        for (int d4 = 0; d4 < 16; d4++) {
            const float* qb = qp0 + 4 * d4;
            ulonglong2 aq0 = *(const ulonglong2*)(qb);
            ulonglong2 aq1 = *(const ulonglong2*)(qb + qtstep);
            ulonglong2 aq2 = *(const ulonglong2*)(qb + 2 * qtstep);
            ulonglong2 aq3 = *(const ulonglong2*)(qb + 3 * qtstep);
            #pragma unroll
            for (int j = 0; j < 8; j++) {
                int s = lane + 32 * j;
                ulonglong2 k2 = *(const ulonglong2*)(Ks + s * KST + 4 * d4);
                sc2[0][j] = fma2(aq0.x, k2.x, sc2[0][j]);
                sc2[0][j] = fma2(aq0.y, k2.y, sc2[0][j]);
                sc2[1][j] = fma2(aq1.x, k2.x, sc2[1][j]);
                sc2[1][j] = fma2(aq1.y, k2.y, sc2[1][j]);
                sc2[2][j] = fma2(aq2.x, k2.x, sc2[2][j]);
                sc2[2][j] = fma2(aq2.y, k2.y, sc2[2][j]);
                sc2[3][j] = fma2(aq3.x, k2.x, sc2[3][j]);
                sc2[3][j] = fma2(aq3.y, k2.y, sc2[3][j]);
            }
        }

        #pragma unroll
        for (int q = 0; q < 4; q++) {
            float pr[8];
            const float* mrow = mask + (size_t)(t0 + q) * SEQ;
            #pragma unroll
            for (int j = 0; j < 8; j++) {
                float lo, hi;
                unpack2(sc2[q][j], lo, hi);
                pr[j] = (lo + hi) * 0.125f + mrow[lane + 32 * j];
            }
            float mx = pr[0];
            #pragma unroll
            for (int j = 1; j < 8; j++) mx = fmaxf(mx, pr[j]);
            #pragma unroll
            for (int o = 16; o; o >>= 1) mx = fmaxf(mx, __shfl_xor_sync(0xffffffffu, mx, o));
            float sum = 0.0f;
            #pragma unroll
            for (int j = 0; j < 8; j++) { pr[j] = __expf(pr[j] - mx); sum += pr[j]; }
            #pragma unroll
            for (int o = 16; o; o >>= 1) sum += __shfl_xor_sync(0xffffffffu, sum, o);
            float inv = 1.0f / sum;
            #pragma unroll
            for (int j = 0; j < 8; j++) Pw[q * SEQ + lane + 32 * j] = pr[j] * inv;
        }
        __syncwarp();

        float2 acc0 = {0, 0}, acc1 = {0, 0}, acc2v = {0, 0}, acc3 = {0, 0};
        const float* vcol = Vs + 2 * lane;
        for (int s = 0; s < SEQ; s++) {
            float2 v2 = *(const float2*)(vcol + s * HD);
            float p0 = Pw[s];
            float p1 = Pw[SEQ + s];
            float p2 = Pw[2 * SEQ + s];
            float p3 = Pw[3 * SEQ + s];
            acc0.x = fmaf(p0, v2.x, acc0.x); acc0.y = fmaf(p0, v2.y, acc0.y);
            acc1.x = fmaf(p1, v2.x, acc1.x); acc1.y = fmaf(p1, v2.y, acc1.y);
            acc2v.x = fmaf(p2, v2.x, acc2v.x); acc2v.y = fmaf(p2, v2.y, acc2v.y);
            acc3.x = fmaf(p3, v2.x, acc3.x); acc3.y = fmaf(p3, v2.y, acc3.y);
        }
        size_t obase = ((size_t)t0 * BATCH + b) * PD + (size_t)h * HD + 2 * lane;
        size_t ostep = (size_t)BATCH * PD;
        float2 accs[4] = {acc0, acc1, acc2v, acc3};
        #pragma unroll
        for (int q = 0; q < 4; q++) {
            size_t oidx = obase + q * ostep;
            __nv_bfloat16 hx = __float2bfloat16_rn(accs[q].x);
            __nv_bfloat16 hy = __float2bfloat16_rn(accs[q].y);
            __nv_bfloat162 h2; h2.x = hx; h2.y = hy;
            __nv_bfloat162 l2;
            l2.x = __float2bfloat16_rn(accs[q].x - __bfloat162float(hx));
            l2.y = __float2bfloat16_rn(accs[q].y - __bfloat162float(hy));
            *(__nv_bfloat162*)(oh + oidx) = h2;
            *(__nv_bfloat162*)(ol + oidx) = l2;
        }
        __syncwarp();
    }
}

// ---------------------------------------------------------------------------
// Host orchestration
// ---------------------------------------------------------------------------
extern "C" void kernel_launch(void* const* d_in, const int* in_sizes, int n_in,
                              void* d_out, int out_size) {
    const float* src  = (const float*)d_in[0];
    const float* mask = (const float*)d_in[1];
    const float* Wqkv = (const float*)d_in[2];
    const float* bqkv = (const float*)d_in[3];
    const float* Wo   = (const float*)d_in[4];
    const float* bo   = (const float*)d_in[5];
    const float* ln1g = (const float*)d_in[6];
    const float* ln1b = (const float*)d_in[7];
    const float* ln2g = (const float*)d_in[8];
    const float* ln2b = (const float*)d_in[9];
    const float* W1   = (const float*)d_in[10];
    const float* b1   = (const float*)d_in[11];
    const float* W2   = (const float*)d_in[12];
    const float* b2   = (const float*)d_in[13];
    const float* lnfg = (const float*)d_in[14];
    const float* lnfb = (const float*)d_in[15];

    float* x = (float*)d_out;

    void *pqkv, *pah, *pal, *pffh, *pffl, *pwh, *pwl;
    cudaGetSymbolAddress(&pqkv, g_qkv);
    cudaGetSymbolAddress(&pah, g_ah);
    cudaGetSymbolAddress(&pal, g_al);
    cudaGetSymbolAddress(&pffh, g_ffh);
    cudaGetSymbolAddress(&pffl, g_ffl);
    cudaGetSymbolAddress(&pwh, g_wh);
    cudaGetSymbolAddress(&pwl, g_wl);
    float* qk = (float*)pqkv;
    __nv_bfloat16* ah  = (__nv_bfloat16*)pah;
    __nv_bfloat16* al  = (__nv_bfloat16*)pal;
    __nv_bfloat16* ffh = (__nv_bfloat16*)pffh;
    __nv_bfloat16* ffl = (__nv_bfloat16*)pffl;
    __nv_bfloat16* wh  = (__nv_bfloat16*)pwh;
    __nv_bfloat16* wl  = (__nv_bfloat16*)pwl;

    cudaFuncSetAttribute(attn_kernel, cudaFuncAttributeMaxDynamicSharedMemorySize,
                         ATTN_SMEM);
    cudaFuncSetAttribute(tc_gemm<0>, cudaFuncAttributeMaxDynamicSharedMemorySize,
                         GEMM_SMEM);
    cudaFuncSetAttribute(tc_gemm<1>, cudaFuncAttributeMaxDynamicSharedMemorySize,
                         GEMM_SMEM);
    cudaFuncSetAttribute(tc_gemm<2>, cudaFuncAttributeMaxDynamicSharedMemorySize,
                         GEMM_SMEM);

    // x = src
    copy_kernel<<<ROWS * NF / (256 * 4), 256>>>(src, x);

    dim3 gQKV(3 * PD / 128, ROWS / 128);   // (24, 64)
    dim3 gWO(NF / 128, ROWS / 128);        // (8, 64)
    dim3 gW1(FF / 128, ROWS / 128);        // (32, 64)
    dim3 gW2(NF / 128, ROWS / 128);        // (8, 64)

    for (int l = 0; l < LAYERS; l++) {
        const float* wqkv = Wqkv + (size_t)l * 3 * PD * NF;
        const float* bq   = bqkv + (size_t)l * 3 * PD;
        const float* wo   = Wo   + (size_t)l * NF * PD;
        const float* bo_  = bo   + (size_t)l * NF;
        const float* w1   = W1   + (size_t)l * FF * NF;
        const float* bb1  = b1   + (size_t)l * FF;
        const float* w2   = W2   + (size_t)l * NF * FF;
        const float* bb2  = b2   + (size_t)l * NF;

        // --- attention block ---
        ln_kernel<1><<<ROWS, 256>>>(x, ln1g + (size_t)l * NF, ln1b + (size_t)l * NF,
                                    nullptr, ah, al);
        convw_kernel<<<(3 * PD * NF) / 1024, 256>>>(wqkv, wh, wl);
        tc_gemm<0><<<gQKV, 256, GEMM_SMEM>>>(ah, al, wh, wl, bq, qk,
                                             nullptr, nullptr, 3 * PD, NF);
        attn_kernel<<<BATCH * NH, 512, ATTN_SMEM>>>(qk, mask, ah, al);
        convw_kernel<<<(NF * PD) / 1024, 256>>>(wo, wh, wl);
        tc_gemm<2><<<gWO, 256, GEMM_SMEM>>>(ah, al, wh, wl, bo_, x,
                                            nullptr, nullptr, NF, PD);

        // --- FFN block ---
        ln_kernel<1><<<ROWS, 256>>>(x, ln2g + (size_t)l * NF, ln2b + (size_t)l * NF,
                                    nullptr, ah, al);
        convw_kernel<<<(FF * NF) / 1024, 256>>>(w1, wh, wl);
        tc_gemm<1><<<gW1, 256, GEMM_SMEM>>>(ah, al, wh, wl, bb1, nullptr,
                                            ffh, ffl, FF, NF);
        convw_kernel<<<(NF * FF) / 1024, 256>>>(w2, wh, wl);
        tc_gemm<2><<<gW2, 256, GEMM_SMEM>>>(ffh, ffl, wh, wl, bb2, x,
                                            nullptr, nullptr, NF, FF);
    }

    // final LN (fp32, in-place on d_out)
    ln_kernel<0><<<ROWS, 256>>>(x, lnfg, lnfb, x, nullptr, nullptr);
}

// round 11
// speedup vs baseline: 2.3663x; 1.0267x over previous
#include <cuda_runtime.h>
#include <cuda_bf16.h>
#include <cstdint>

// ---------------------------------------------------------------------------
// Problem constants
// ---------------------------------------------------------------------------
#define LAYERS 6
#define SEQ    256
#define BATCH  32
#define NF     1024
#define NH     16
#define HD     64
#define PD     1024
#define FF     4096
#define ROWS   (SEQ*BATCH)     // 8192
#define EPSLN  1e-5f

// ---------------------------------------------------------------------------
// Scratch (device globals; allocation-free per harness rules)
// ---------------------------------------------------------------------------
__device__ float          g_qkv[(size_t)ROWS * 3 * PD];
__device__ __nv_bfloat16  g_ah [(size_t)ROWS * NF];
__device__ __nv_bfloat16  g_al [(size_t)ROWS * NF];
__device__ __nv_bfloat16  g_ffh[(size_t)ROWS * FF];
__device__ __nv_bfloat16  g_ffl[(size_t)ROWS * FF];
__device__ __nv_bfloat16  g_wh [(size_t)FF * NF];
__device__ __nv_bfloat16  g_wl [(size_t)FF * NF];

// ---------------------------------------------------------------------------
// PTX helpers (base sm_103 instruction set ONLY)
// ---------------------------------------------------------------------------
__device__ __forceinline__ uint32_t smem_u32(const void* p) {
    uint32_t a;
    asm("{ .reg .u64 t; cvta.to.shared.u64 t, %1; cvt.u32.u64 %0, t; }"
        : "=r"(a) : "l"(p));
    return a;
}
__device__ __forceinline__ void cp_async16(uint32_t saddr, const void* gaddr) {
    asm volatile("cp.async.cg.shared.global [%0], [%1], 16;"
                 :: "r"(saddr), "l"(gaddr) : "memory");
}
__device__ __forceinline__ void cp_commit() {
    asm volatile("cp.async.commit_group;" ::: "memory");
}
template <int N>
__device__ __forceinline__ void cp_wait() {
    asm volatile("cp.async.wait_group %0;" :: "n"(N) : "memory");
}
__device__ __forceinline__ void ldsm_x4(uint32_t* r, uint32_t addr) {
    asm volatile("ldmatrix.sync.aligned.m8n8.x4.shared.b16 {%0,%1,%2,%3}, [%4];"
                 : "=r"(r[0]), "=r"(r[1]), "=r"(r[2]), "=r"(r[3]) : "r"(addr));
}
__device__ __forceinline__ void mma16816(float* c, const uint32_t* a, const uint32_t* b) {
    asm volatile(
        "mma.sync.aligned.m16n8k16.row.col.f32.bf16.bf16.f32 "
        "{%0,%1,%2,%3}, {%4,%5,%6,%7}, {%8,%9}, {%0,%1,%2,%3};"
        : "+f"(c[0]), "+f"(c[1]), "+f"(c[2]), "+f"(c[3])
        : "r"(a[0]), "r"(a[1]), "r"(a[2]), "r"(a[3]), "r"(b[0]), "r"(b[1]));
}

// f32x2 helpers for attention
__device__ __forceinline__ unsigned long long fma2(unsigned long long a,
                                                   unsigned long long b,
                                                   unsigned long long c) {
    unsigned long long d;
    asm("fma.rn.f32x2 %0, %1, %2, %3;" : "=l"(d) : "l"(a), "l"(b), "l"(c));
    return d;
}
__device__ __forceinline__ void unpack2(unsigned long long v, float& lo, float& hi) {
    asm("mov.b64 {%0, %1}, %2;" : "=f"(lo), "=f"(hi) : "l"(v));
}

// ---------------------------------------------------------------------------
// Utility kernels
// ---------------------------------------------------------------------------
__global__ __launch_bounds__(256) void copy_kernel(const float* __restrict__ src,
                                                   float* __restrict__ dst) {
    size_t i = (size_t)blockIdx.x * 256 + threadIdx.x;
    ((float4*)dst)[i] = ((const float4*)src)[i];
}

// fp32 -> bf16 hi/lo split (weights)
__global__ __launch_bounds__(256) void convw_kernel(const float* __restrict__ w,
                                                    __nv_bfloat16* __restrict__ hi,
                                                    __nv_bfloat16* __restrict__ lo) {
    size_t i = (size_t)blockIdx.x * 256 + threadIdx.x;
    float4 v = ((const float4*)w)[i];
    __nv_bfloat16 hx = __float2bfloat16_rn(v.x);
    __nv_bfloat16 hy = __float2bfloat16_rn(v.y);
    __nv_bfloat16 hz = __float2bfloat16_rn(v.z);
    __nv_bfloat16 hw = __float2bfloat16_rn(v.w);
    __nv_bfloat162 h0; h0.x = hx; h0.y = hy;
    __nv_bfloat162 h1; h1.x = hz; h1.y = hw;
    __nv_bfloat162 l0, l1;
    l0.x = __float2bfloat16_rn(v.x - __bfloat162float(hx));
    l0.y = __float2bfloat16_rn(v.y - __bfloat162float(hy));
    l1.x = __float2bfloat16_rn(v.z - __bfloat162float(hz));
    l1.y = __float2bfloat16_rn(v.w - __bfloat162float(hw));
    ((__nv_bfloat162*)hi)[2 * i]     = h0;
    ((__nv_bfloat162*)hi)[2 * i + 1] = h1;
    ((__nv_bfloat162*)lo)[2 * i]     = l0;
    ((__nv_bfloat162*)lo)[2 * i + 1] = l1;
}

// ---------------------------------------------------------------------------
// LayerNorm over N=1024. MODE 0: fp32 out. MODE 1: bf16 hi/lo out.
// ---------------------------------------------------------------------------
template <int MODE>
__global__ __launch_bounds__(256) void ln_kernel(const float* __restrict__ x,
                                                 const float* __restrict__ g,
                                                 const float* __restrict__ b,
                                                 float* __restrict__ y,
                                                 __nv_bfloat16* __restrict__ oh,
                                                 __nv_bfloat16* __restrict__ ol) {
    int row = blockIdx.x;
    int t   = threadIdx.x;
    const float4* xr = (const float4*)(x + (size_t)row * NF);
    float4 v = xr[t];

    __shared__ float red[8];
    float s = v.x + v.y + v.z + v.w;
    #pragma unroll
    for (int o = 16; o; o >>= 1) s += __shfl_xor_sync(0xffffffffu, s, o);
    if ((t & 31) == 0) red[t >> 5] = s;
    __syncthreads();
    float tot = red[0] + red[1] + red[2] + red[3] + red[4] + red[5] + red[6] + red[7];
    float mean = tot * (1.0f / NF);
    __syncthreads();

    float dx = v.x - mean, dy = v.y - mean, dz = v.z - mean, dw = v.w - mean;
    float sq = dx * dx + dy * dy + dz * dz + dw * dw;
    #pragma unroll
    for (int o = 16; o; o >>= 1) sq += __shfl_xor_sync(0xffffffffu, sq, o);
    if ((t & 31) == 0) red[t >> 5] = sq;
    __syncthreads();
    float vtot = red[0] + red[1] + red[2] + red[3] + red[4] + red[5] + red[6] + red[7];
    float inv = rsqrtf(vtot * (1.0f / NF) + EPSLN);

    float4 gg = ((const float4*)g)[t];
    float4 bb = ((const float4*)b)[t];
    float4 out;
    out.x = dx * inv * gg.x + bb.x;
    out.y = dy * inv * gg.y + bb.y;
    out.z = dz * inv * gg.z + bb.z;
    out.w = dw * inv * gg.w + bb.w;

    if (MODE == 0) {
        ((float4*)(y + (size_t)row * NF))[t] = out;
    } else {
        size_t base = (size_t)row * NF + (size_t)t * 4;
        __nv_bfloat16 hx = __float2bfloat16_rn(out.x);
        __nv_bfloat16 hy = __float2bfloat16_rn(out.y);
        __nv_bfloat16 hz = __float2bfloat16_rn(out.z);
        __nv_bfloat16 hw = __float2bfloat16_rn(out.w);
        __nv_bfloat162 h0; h0.x = hx; h0.y = hy;
        __nv_bfloat162 h1; h1.x = hz; h1.y = hw;
        __nv_bfloat162 l0, l1;
        l0.x = __float2bfloat16_rn(out.x - __bfloat162float(hx));
        l0.y = __float2bfloat16_rn(out.y - __bfloat162float(hy));
        l1.x = __float2bfloat16_rn(out.z - __bfloat162float(hz));
        l1.y = __float2bfloat16_rn(out.w - __bfloat162float(hw));
        *(__nv_bfloat162*)(oh + base)     = h0;
        *(__nv_bfloat162*)(oh + base + 2) = h1;
        *(__nv_bfloat162*)(ol + base)     = l0;
        *(__nv_bfloat162*)(ol + base + 2) = l1;
    }
}

// ---------------------------------------------------------------------------
// HMMA GEMM: C[M,Nn] = (Ah+Al)[M,K] @ (Wh+Wl)[Nn,K]^T (+bias)(+epilogue)
// via mma.sync m16n8k16 bf16, products AhWh + AhWl + AlWh.
// CTA tile 128x128, 16 warps (4x4), warp tile 32x32, K-chunk 64,
// 3-stage cp.async ring, ONE __syncthreads per chunk.
// Order per chunk: cp_wait -> __syncthreads -> compute -> issue next+2.
// EPI 0: bias, fp32 store. EPI 1: bias+relu -> bf16 hi/lo. EPI 2: C += acc+bias.
// ---------------------------------------------------------------------------
#define KC   64
#define AST  72                       // padded row length (bf16 elems)
#define ARB  (AST*2)                  // 144 bytes/row
#define TILEB (128*ARB)               // 18432 B per array tile
#define STAGEB (4*TILEB)              // 73728 B per stage (Ah|Al|Wh|Wl)
#define NSTAGE 3
#define GEMM_SMEM (NSTAGE*STAGEB)     // 221184 B

__device__ __forceinline__ void gemm_issue_chunk(
    const __nv_bfloat16* pAh, const __nv_bfloat16* pAl,
    const __nv_bfloat16* pWh, const __nv_bfloat16* pWl,
    int K, int c, uint32_t dst0, int tid) {
    const __nv_bfloat16* srcs[4] = {pAh + (size_t)c * KC, pAl + (size_t)c * KC,
                                    pWh + (size_t)c * KC, pWl + (size_t)c * KC};
    #pragma unroll
    for (int arr = 0; arr < 4; arr++) {
        const __nv_bfloat16* p = srcs[arr];
        uint32_t d0 = dst0 + arr * TILEB;
        #pragma unroll
        for (int i = 0; i < 2; i++) {
            int idx = i * 512 + tid;
            int r = idx >> 3, cc = idx & 7;
            cp_async16(d0 + r * ARB + cc * 16, p + (size_t)r * K + cc * 8);
        }
    }
    cp_commit();
}

template <int EPI>
__global__ __launch_bounds__(512, 1)
void tc_gemm(const __nv_bfloat16* __restrict__ Ah, const __nv_bfloat16* __restrict__ Al,
             const __nv_bfloat16* __restrict__ Wh, const __nv_bfloat16* __restrict__ Wl,
             const float* __restrict__ bias, float* __restrict__ C,
             __nv_bfloat16* __restrict__ Oh, __nv_bfloat16* __restrict__ Ol,
             int Nn, int K) {
    extern __shared__ __align__(16) char smem[];
    __shared__ float sbias[128];
    uint32_t sb = smem_u32(smem);
    int tid = threadIdx.x;
    int bm = blockIdx.y * 128;
    int bn = blockIdx.x * 128;

    if (tid < 128) sbias[tid] = bias[bn + tid];

    const __nv_bfloat16* pAh = Ah + (size_t)bm * K;
    const __nv_bfloat16* pAl = Al + (size_t)bm * K;
    const __nv_bfloat16* pWh = Wh + (size_t)bn * K;
    const __nv_bfloat16* pWl = Wl + (size_t)bn * K;

    int l = tid & 31, warp = tid >> 5;
    int wm = warp >> 2, wn = warp & 3;       // 4x4 warps, warp tile 32x32

    float acc[2][4][4];
    #pragma unroll
    for (int i = 0; i < 2; i++)
        #pragma unroll
        for (int j = 0; j < 4; j++)
            #pragma unroll
            for (int k = 0; k < 4; k++) acc[i][j][k] = 0.0f;

    // ldmatrix lane addressing
    // A x4 (m16k16 tile): lanes 0-15 -> rows, k-lo; lanes 16-31 -> rows, k-hi
    int arow  = wm * 32 + (l & 15);
    int acolb = (l >> 4) * 16;
    // B paired x4 (two n8k16 tiles): mat0/1 = j0 k-lo/k-hi, mat2/3 = j1 k-lo/k-hi
    int brow  = wn * 32 + ((l >> 4) & 1) * 8 + (l & 7);
    int bcolb = ((l >> 3) & 1) * 16;

    int NC = K / KC;

    gemm_issue_chunk(pAh, pAl, pWh, pWl, K, 0, sb, tid);
    gemm_issue_chunk(pAh, pAl, pWh, pWl, K, 1, sb + STAGEB, tid);

    int stage = 0;
    for (int c = 0; c < NC; c++) {
        // wait for chunk c's copies (own), then barrier to publish ALL threads'
        // copies AND prove all warps finished chunk c-1 (stage reuse safety).
        if (c + 1 < NC) cp_wait<1>(); else cp_wait<0>();
        __syncthreads();

        uint32_t sA  = sb + stage * STAGEB;
        uint32_t sAl = sA + TILEB;
        uint32_t sW  = sA + 2 * TILEB;
        uint32_t sWl = sA + 3 * TILEB;

        #pragma unroll
        for (int ks = 0; ks < KC / 16; ks++) {
            uint32_t ah[2][4], al4[2][4], wh[2][4], wl4[2][4];
            #pragma unroll
            for (int i = 0; i < 2; i++) {
                uint32_t off = (uint32_t)(arow + i * 16) * ARB + ks * 32 + acolb;
                ldsm_x4(ah[i],  sA  + off);
                ldsm_x4(al4[i], sAl + off);
            }
            #pragma unroll
            for (int jp = 0; jp < 2; jp++) {
                uint32_t off = (uint32_t)(brow + jp * 16) * ARB + ks * 32 + bcolb;
                ldsm_x4(wh[jp],  sW  + off);
                ldsm_x4(wl4[jp], sWl + off);
            }
            #pragma unroll
            for (int i = 0; i < 2; i++)
                #pragma unroll
                for (int j = 0; j < 4; j++) {
                    const uint32_t* bh = &wh[j >> 1][(j & 1) * 2];
                    const uint32_t* bl = &wl4[j >> 1][(j & 1) * 2];
                    mma16816(acc[i][j], ah[i],  bh);
                    mma16816(acc[i][j], ah[i],  bl);
                    mma16816(acc[i][j], al4[i], bh);
                }
        }

        // issue chunk c+2 into the stage that held chunk c-1 (drained by the
        // barrier above, executed by every thread after finishing chunk c-1).
        if (c + 2 < NC) {
            int ns = stage + 2; if (ns >= NSTAGE) ns -= NSTAGE;
            gemm_issue_chunk(pAh, pAl, pWh, pWl, K, c + 2, sb + ns * STAGEB, tid);
        }
        if (++stage >= NSTAGE) stage = 0;
    }

    // epilogue: fragment (c0,c1)->(row,col..col+1); (c2,c3)->(row+8,..)
    int r0 = bm + wm * 32 + (l >> 2);
    int cb = wn * 32 + 2 * (l & 3);
    #pragma unroll
    for (int i = 0; i < 2; i++) {
        #pragma unroll
        for (int j = 0; j < 4; j++) {
            int col = cb + j * 8;
            float b0 = sbias[col], b1 = sbias[col + 1];
            #pragma unroll
            for (int half = 0; half < 2; half++) {
                int m = r0 + i * 16 + half * 8;
                float v0 = acc[i][j][2 * half]     + b0;
                float v1 = acc[i][j][2 * half + 1] + b1;
                size_t idx = (size_t)m * Nn + bn + col;
                if (EPI == 0) {
                    float2 s = {v0, v1};
                    *(float2*)(C + idx) = s;
                } else if (EPI == 2) {
                    float2 old = *(const float2*)(C + idx);
                    float2 s = {v0 + old.x, v1 + old.y};
                    *(float2*)(C + idx) = s;
                } else {  // EPI 1: relu -> bf16 hi/lo split
                    v0 = fmaxf(v0, 0.0f);
                    v1 = fmaxf(v1, 0.0f);
                    __nv_bfloat16 h0 = __float2bfloat16_rn(v0);
                    __nv_bfloat16 h1 = __float2bfloat16_rn(v1);
                    __nv_bfloat162 h2; h2.x = h0; h2.y = h1;
                    __nv_bfloat162 l2;
                    l2.x = __float2bfloat16_rn(v0 - __bfloat162float(h0));
                    l2.y = __float2bfloat16_rn(v1 - __bfloat162float(h1));
                    *(__nv_bfloat162*)(Oh + idx) = h2;
                    *(__nv_bfloat162*)(Ol + idx) = l2;
                }
            }
        }
    }
}

// ---------------------------------------------------------------------------
// Fused attention: one CTA per (b,h), 512 threads, K/V resident in SMEM.
// ---------------------------------------------------------------------------
#define KST 68
#define ATTN_SMEM ((SEQ*KST + SEQ*HD + 16*4*SEQ) * 4)

__global__ __launch_bounds__(512, 1) void attn_kernel(const float* __restrict__ qkv,
                                                      const float* __restrict__ mask,
                                                      __nv_bfloat16* __restrict__ oh,
                                                      __nv_bfloat16* __restrict__ ol) {
    extern __shared__ __align__(16) float sm[];
    float* Ks = sm;
    float* Vs = Ks + SEQ * KST;
    float* Ps = Vs + SEQ * HD;

    int bh = blockIdx.x;
    int b  = bh >> 4;
    int h  = bh & 15;
    int tid = threadIdx.x;

    for (int idx = tid; idx < SEQ * 16; idx += 512) {
        int s = idx >> 4;
        int c = (idx & 15) << 2;
        size_t base = ((size_t)s * BATCH + b) * (3 * PD) + (size_t)h * HD + c;
        float4 k4 = *(const float4*)(qkv + base + PD);
        float4 v4 = *(const float4*)(qkv + base + 2 * PD);
        *(float4*)(Ks + s * KST + c) = k4;
        *(float4*)(Vs + s * HD + c) = v4;
    }
    __syncthreads();

    int warp = tid >> 5, lane = tid & 31;
    float* Pw = Ps + warp * 4 * SEQ;
    const size_t qtstep = (size_t)BATCH * 3 * PD;

    for (int it = 0; it < 4; it++) {
        int t0 = warp * 16 + it * 4;
        const float* qp0 = qkv + ((size_t)t0 * BATCH + b) * (3 * PD) + (size_t)h * HD;

        unsigned long long sc2[4][8];
        #pragma unroll
        for (int q = 0; q < 4; q++)
            #pragma unroll
            for (int j = 0; j < 8; j++) sc2[q][j] = 0ull;

        #pragma unroll 2
        for (int d4 = 0; d4 < 16; d4++) {
            const float* qb = qp0 + 4 * d4;
            ulonglong2 aq0 = *(const ulonglong2*)(qb);
            ulonglong2 aq1 = *(const ulonglong2*)(qb + qtstep);
            ulonglong2 aq2 = *(const ulonglong2*)(qb + 2 * qtstep);
            ulonglong2 aq3 = *(const ulonglong2*)(qb + 3 * qtstep);
            #pragma unroll
            for (int j = 0; j < 8; j++) {
                int s = lane + 32 * j;
                ulonglong2 k2 = *(const ulonglong2*)(Ks + s * KST + 4 * d4);
                sc2[0][j] = fma2(aq0.x, k2.x, sc2[0][j]);
                sc2[0][j] = fma2(aq0.y, k2.y, sc2[0][j]);
                sc2[1][j] = fma2(aq1.x, k2.x, sc2[1][j]);
                sc2[1][j] = fma2(aq1.y, k2.y, sc2[1][j]);
                sc2[2][j] = fma2(aq2.x, k2.x, sc2[2][j]);
                sc2[2][j] = fma2(aq2.y, k2.y, sc2[2][j]);
                sc2[3][j] = fma2(aq3.x, k2.x, sc2[3][j]);
                sc2[3][j] = fma2(aq3.y, k2.y, sc2[3][j]);
            }
        }

        #pragma unroll
        for (int q = 0; q < 4; q++) {
            float pr[8];
            const float* mrow = mask + (size_t)(t0 + q) * SEQ;
            #pragma unroll
            for (int j = 0; j < 8; j++) {
                float lo, hi;
                unpack2(sc2[q][j], lo, hi);
                pr[j] = (lo + hi) * 0.125f + mrow[lane + 32 * j];
            }
            float mx = pr[0];
            #pragma unroll
            for (int j = 1; j < 8; j++) mx = fmaxf(mx, pr[j]);
            #pragma unroll
            for (int o = 16; o; o >>= 1) mx = fmaxf(mx, __shfl_xor_sync(0xffffffffu, mx, o));
            float sum = 0.0f;
            #pragma unroll
            for (int j = 0; j < 8; j++) { pr[j] = __expf(pr[j] - mx); sum += pr[j]; }
            #pragma unroll
            for (int o = 16; o; o >>= 1) sum += __shfl_xor_sync(0xffffffffu, sum, o);
            float inv = 1.0f / sum;
            #pragma unroll
            for (int j = 0; j < 8; j++) Pw[q * SEQ + lane + 32 * j] = pr[j] * inv;
        }
        __syncwarp();

        float2 acc0 = {0, 0}, acc1 = {0, 0}, acc2v = {0, 0}, acc3 = {0, 0};
        const float* vcol = Vs + 2 * lane;
        for (int s = 0; s < SEQ; s++) {
            float2 v2 = *(const float2*)(vcol + s * HD);
            float p0 = Pw[s];
            float p1 = Pw[SEQ + s];
            float p2 = Pw[2 * SEQ + s];
            float p3 = Pw[3 * SEQ + s];
            acc0.x = fmaf(p0, v2.x, acc0.x); acc0.y = fmaf(p0, v2.y, acc0.y);
            acc1.x = fmaf(p1, v2.x, acc1.x); acc1.y = fmaf(p1, v2.y, acc1.y);
            acc2v.x = fmaf(p2, v2.x, acc2v.x); acc2v.y = fmaf(p2, v2.y, acc2v.y);
            acc3.x = fmaf(p3, v2.x, acc3.x); acc3.y = fmaf(p3, v2.y, acc3.y);
        }
        size_t obase = ((size_t)t0 * BATCH + b) * PD + (size_t)h * HD + 2 * lane;
        size_t ostep = (size_t)BATCH * PD;
        float2 accs[4] = {acc0, acc1, acc2v, acc3};
        #pragma unroll
        for (int q = 0; q < 4; q++) {
            size_t oidx = obase + q * ostep;
            __nv_bfloat16 hx = __float2bfloat16_rn(accs[q].x);
            __nv_bfloat16 hy = __float2bfloat16_rn(accs[q].y);
            __nv_bfloat162 h2; h2.x = hx; h2.y = hy;
            __nv_bfloat162 l2;
            l2.x = __float2bfloat16_rn(accs[q].x - __bfloat162float(hx));
            l2.y = __float2bfloat16_rn(accs[q].y - __bfloat162float(hy));
            *(__nv_bfloat162*)(oh + oidx) = h2;
            *(__nv_bfloat162*)(ol + oidx) = l2;
        }
        __syncwarp();
    }
}

// ---------------------------------------------------------------------------
// Host orchestration
// ---------------------------------------------------------------------------
extern "C" void kernel_launch(void* const* d_in, const int* in_sizes, int n_in,
                              void* d_out, int out_size) {
    const float* src  = (const float*)d_in[0];
    const float* mask = (const float*)d_in[1];
    const float* Wqkv = (const float*)d_in[2];
    const float* bqkv = (const float*)d_in[3];
    const float* Wo   = (const float*)d_in[4];
    const float* bo   = (const float*)d_in[5];
    const float* ln1g = (const float*)d_in[6];
    const float* ln1b = (const float*)d_in[7];
    const float* ln2g = (const float*)d_in[8];
    const float* ln2b = (const float*)d_in[9];
    const float* W1   = (const float*)d_in[10];
    const float* b1   = (const float*)d_in[11];
    const float* W2   = (const float*)d_in[12];
    const float* b2   = (const float*)d_in[13];
    const float* lnfg = (const float*)d_in[14];
    const float* lnfb = (const float*)d_in[15];

    float* x = (float*)d_out;

    void *pqkv, *pah, *pal, *pffh, *pffl, *pwh, *pwl;
    cudaGetSymbolAddress(&pqkv, g_qkv);
    cudaGetSymbolAddress(&pah, g_ah);
    cudaGetSymbolAddress(&pal, g_al);
    cudaGetSymbolAddress(&pffh, g_ffh);
    cudaGetSymbolAddress(&pffl, g_ffl);
    cudaGetSymbolAddress(&pwh, g_wh);
    cudaGetSymbolAddress(&pwl, g_wl);
    float* qk = (float*)pqkv;
    __nv_bfloat16* ah  = (__nv_bfloat16*)pah;
    __nv_bfloat16* al  = (__nv_bfloat16*)pal;
    __nv_bfloat16* ffh = (__nv_bfloat16*)pffh;
    __nv_bfloat16* ffl = (__nv_bfloat16*)pffl;
    __nv_bfloat16* wh  = (__nv_bfloat16*)pwh;
    __nv_bfloat16* wl  = (__nv_bfloat16*)pwl;

    cudaFuncSetAttribute(attn_kernel, cudaFuncAttributeMaxDynamicSharedMemorySize,
                         ATTN_SMEM);
    cudaFuncSetAttribute(tc_gemm<0>, cudaFuncAttributeMaxDynamicSharedMemorySize,
                         GEMM_SMEM);
    cudaFuncSetAttribute(tc_gemm<1>, cudaFuncAttributeMaxDynamicSharedMemorySize,
                         GEMM_SMEM);
    cudaFuncSetAttribute(tc_gemm<2>, cudaFuncAttributeMaxDynamicSharedMemorySize,
                         GEMM_SMEM);

    // x = src
    copy_kernel<<<ROWS * NF / (256 * 4), 256>>>(src, x);

    dim3 gQKV(3 * PD / 128, ROWS / 128);   // (24, 64)
    dim3 gWO(NF / 128, ROWS / 128);        // (8, 64)
    dim3 gW1(FF / 128, ROWS / 128);        // (32, 64)
    dim3 gW2(NF / 128, ROWS / 128);        // (8, 64)

    for (int l = 0; l < LAYERS; l++) {
        const float* wqkv = Wqkv + (size_t)l * 3 * PD * NF;
        const float* bq   = bqkv + (size_t)l * 3 * PD;
        const float* wo   = Wo   + (size_t)l * NF * PD;
        const float* bo_  = bo   + (size_t)l * NF;
        const float* w1   = W1   + (size_t)l * FF * NF;
        const float* bb1  = b1   + (size_t)l * FF;
        const float* w2   = W2   + (size_t)l * NF * FF;
        const float* bb2  = b2   + (size_t)l * NF;

        // --- attention block ---
        ln_kernel<1><<<ROWS, 256>>>(x, ln1g + (size_t)l * NF, ln1b + (size_t)l * NF,
                                    nullptr, ah, al);
        convw_kernel<<<(3 * PD * NF) / 1024, 256>>>(wqkv, wh, wl);
        tc_gemm<0><<<gQKV, 512, GEMM_SMEM>>>(ah, al, wh, wl, bq, qk,
                                             nullptr, nullptr, 3 * PD, NF);
        attn_kernel<<<BATCH * NH, 512, ATTN_SMEM>>>(qk, mask, ah, al);
        convw_kernel<<<(NF * PD) / 1024, 256>>>(wo, wh, wl);
        tc_gemm<2><<<gWO, 512, GEMM_SMEM>>>(ah, al, wh, wl, bo_, x,
                                            nullptr, nullptr, NF, PD);

        // --- FFN block ---
        ln_kernel<1><<<ROWS, 256>>>(x, ln2g + (size_t)l * NF, ln2b + (size_t)l * NF,
                                    nullptr, ah, al);
        convw_kernel<<<(FF * NF) / 1024, 256>>>(w1, wh, wl);
        tc_gemm<1><<<gW1, 512, GEMM_SMEM>>>(ah, al, wh, wl, bb1, nullptr,
                                            ffh, ffl, FF, NF);
        convw_kernel<<<(NF * FF) / 1024, 256>>>(w2, wh, wl);
        tc_gemm<2><<<gW2, 512, GEMM_SMEM>>>(ffh, ffl, wh, wl, bb2, x,
                                            nullptr, nullptr, NF, FF);
    }

    // final LN (fp32, in-place on d_out)
    ln_kernel<0><<<ROWS, 256>>>(x, lnfg, lnfb, x, nullptr, nullptr);
}

// round 12
// speedup vs baseline: 2.4014x; 1.0149x over previous
#include <cuda_runtime.h>
#include <cuda_fp16.h>
#include <cstdint>

// ---------------------------------------------------------------------------
// Problem constants
// ---------------------------------------------------------------------------
#define LAYERS 6
#define SEQ    256
#define BATCH  32
#define NF     1024
#define NH     16
#define HD     64
#define PD     1024
#define FF     4096
#define ROWS   (SEQ*BATCH)     // 8192
#define EPSLN  1e-5f

// ---------------------------------------------------------------------------
// Scratch (device globals; allocation-free per harness rules)
// ---------------------------------------------------------------------------
__device__ float   g_qkv[(size_t)ROWS * 3 * PD];
__device__ __half  g_ah [(size_t)ROWS * NF];
__device__ __half  g_al [(size_t)ROWS * NF];
__device__ __half  g_ffh[(size_t)ROWS * FF];
__device__ __half  g_ffl[(size_t)ROWS * FF];
__device__ __half  g_wh [(size_t)FF * NF];
__device__ __half  g_wl [(size_t)FF * NF];

// ---------------------------------------------------------------------------
// PTX helpers (base sm_103 instruction set ONLY)
// ---------------------------------------------------------------------------
__device__ __forceinline__ uint32_t smem_u32(const void* p) {
    uint32_t a;
    asm("{ .reg .u64 t; cvta.to.shared.u64 t, %1; cvt.u32.u64 %0, t; }"
        : "=r"(a) : "l"(p));
    return a;
}
__device__ __forceinline__ void cp_async16(uint32_t saddr, const void* gaddr) {
    asm volatile("cp.async.cg.shared.global [%0], [%1], 16;"
                 :: "r"(saddr), "l"(gaddr) : "memory");
}
__device__ __forceinline__ void cp_commit() {
    asm volatile("cp.async.commit_group;" ::: "memory");
}
template <int N>
__device__ __forceinline__ void cp_wait() {
    asm volatile("cp.async.wait_group %0;" :: "n"(N) : "memory");
}
__device__ __forceinline__ void ldsm_x4(uint32_t* r, uint32_t addr) {
    asm volatile("ldmatrix.sync.aligned.m8n8.x4.shared.b16 {%0,%1,%2,%3}, [%4];"
                 : "=r"(r[0]), "=r"(r[1]), "=r"(r[2]), "=r"(r[3]) : "r"(addr));
}
// fp16 inputs, fp32 accumulators (main term)
__device__ __forceinline__ void mma_f32acc(float* c, const uint32_t* a, const uint32_t* b) {
    asm volatile(
        "mma.sync.aligned.m16n8k16.row.col.f32.f16.f16.f32 "
        "{%0,%1,%2,%3}, {%4,%5,%6,%7}, {%8,%9}, {%0,%1,%2,%3};"
        : "+f"(c[0]), "+f"(c[1]), "+f"(c[2]), "+f"(c[3])
        : "r"(a[0]), "r"(a[1]), "r"(a[2]), "r"(a[3]), "r"(b[0]), "r"(b[1]));
}
// fp16 inputs, fp16 accumulators (correction terms; 2x rate if fp32-acc is half-rate)
__device__ __forceinline__ void mma_f16acc(uint32_t* c, const uint32_t* a, const uint32_t* b) {
    asm volatile(
        "mma.sync.aligned.m16n8k16.row.col.f16.f16.f16.f16 "
        "{%0,%1}, {%2,%3,%4,%5}, {%6,%7}, {%0,%1};"
        : "+r"(c[0]), "+r"(c[1])
        : "r"(a[0]), "r"(a[1]), "r"(a[2]), "r"(a[3]), "r"(b[0]), "r"(b[1]));
}

// f32x2 helpers for attention
__device__ __forceinline__ unsigned long long fma2(unsigned long long a,
                                                   unsigned long long b,
                                                   unsigned long long c) {
    unsigned long long d;
    asm("fma.rn.f32x2 %0, %1, %2, %3;" : "=l"(d) : "l"(a), "l"(b), "l"(c));
    return d;
}
__device__ __forceinline__ void unpack2(unsigned long long v, float& lo, float& hi) {
    asm("mov.b64 {%0, %1}, %2;" : "=f"(lo), "=f"(hi) : "l"(v));
}

// ---------------------------------------------------------------------------
// Utility kernels
// ---------------------------------------------------------------------------
__global__ __launch_bounds__(256) void copy_kernel(const float* __restrict__ src,
                                                   float* __restrict__ dst) {
    size_t i = (size_t)blockIdx.x * 256 + threadIdx.x;
    ((float4*)dst)[i] = ((const float4*)src)[i];
}

// fp32 -> fp16 hi/lo split (weights)
__global__ __launch_bounds__(256) void convw_kernel(const float* __restrict__ w,
                                                    __half* __restrict__ hi,
                                                    __half* __restrict__ lo) {
    size_t i = (size_t)blockIdx.x * 256 + threadIdx.x;
    float4 v = ((const float4*)w)[i];
    __half hx = __float2half_rn(v.x);
    __half hy = __float2half_rn(v.y);
    __half hz = __float2half_rn(v.z);
    __half hw = __float2half_rn(v.w);
    __half2 h0 = __halves2half2(hx, hy);
    __half2 h1 = __halves2half2(hz, hw);
    __half2 l0 = __halves2half2(__float2half_rn(v.x - __half2float(hx)),
                                __float2half_rn(v.y - __half2float(hy)));
    __half2 l1 = __halves2half2(__float2half_rn(v.z - __half2float(hz)),
                                __float2half_rn(v.w - __half2float(hw)));
    ((__half2*)hi)[2 * i]     = h0;
    ((__half2*)hi)[2 * i + 1] = h1;
    ((__half2*)lo)[2 * i]     = l0;
    ((__half2*)lo)[2 * i + 1] = l1;
}

// ---------------------------------------------------------------------------
// LayerNorm over N=1024. MODE 0: fp32 out. MODE 1: fp16 hi/lo out.
// ---------------------------------------------------------------------------
template <int MODE>
__global__ __launch_bounds__(256) void ln_kernel(const float* __restrict__ x,
                                                 const float* __restrict__ g,
                                                 const float* __restrict__ b,
                                                 float* __restrict__ y,
                                                 __half* __restrict__ oh,
                                                 __half* __restrict__ ol) {
    int row = blockIdx.x;
    int t   = threadIdx.x;
    const float4* xr = (const float4*)(x + (size_t)row * NF);
    float4 v = xr[t];

    __shared__ float red[8];
    float s = v.x + v.y + v.z + v.w;
    #pragma unroll
    for (int o = 16; o; o >>= 1) s += __shfl_xor_sync(0xffffffffu, s, o);
    if ((t & 31) == 0) red[t >> 5] = s;
    __syncthreads();
    float tot = red[0] + red[1] + red[2] + red[3] + red[4] + red[5] + red[6] + red[7];
    float mean = tot * (1.0f / NF);
    __syncthreads();

    float dx = v.x - mean, dy = v.y - mean, dz = v.z - mean, dw = v.w - mean;
    float sq = dx * dx + dy * dy + dz * dz + dw * dw;
    #pragma unroll
    for (int o = 16; o; o >>= 1) sq += __shfl_xor_sync(0xffffffffu, sq, o);
    if ((t & 31) == 0) red[t >> 5] = sq;
    __syncthreads();
    float vtot = red[0] + red[1] + red[2] + red[3] + red[4] + red[5] + red[6] + red[7];
    float inv = rsqrtf(vtot * (1.0f / NF) + EPSLN);

    float4 gg = ((const float4*)g)[t];
    float4 bb = ((const float4*)b)[t];
    float4 out;
    out.x = dx * inv * gg.x + bb.x;
    out.y = dy * inv * gg.y + bb.y;
    out.z = dz * inv * gg.z + bb.z;
    out.w = dw * inv * gg.w + bb.w;

    if (MODE == 0) {
        ((float4*)(y + (size_t)row * NF))[t] = out;
    } else {
        size_t base = (size_t)row * NF + (size_t)t * 4;
        __half hx = __float2half_rn(out.x);
        __half hy = __float2half_rn(out.y);
        __half hz = __float2half_rn(out.z);
        __half hw = __float2half_rn(out.w);
        __half2 h0 = __halves2half2(hx, hy);
        __half2 h1 = __halves2half2(hz, hw);
        __half2 l0 = __halves2half2(__float2half_rn(out.x - __half2float(hx)),
                                    __float2half_rn(out.y - __half2float(hy)));
        __half2 l1 = __halves2half2(__float2half_rn(out.z - __half2float(hz)),
                                    __float2half_rn(out.w - __half2float(hw)));
        *(__half2*)(oh + base)     = h0;
        *(__half2*)(oh + base + 2) = h1;
        *(__half2*)(ol + base)     = l0;
        *(__half2*)(ol + base + 2) = l1;
    }
}

// ---------------------------------------------------------------------------
// HMMA GEMM: C[M,Nn] = (Ah+Al)[M,K] @ (Wh+Wl)[Nn,K]^T (+bias)(+epilogue)
// fp16 hi/lo split: main AhWh in fp32 acc; corrections AhWl + AlWh in fp16 acc.
// CTA tile 128x128, 16 warps (4x4), warp tile 32x32, K-chunk 64,
// 3-stage cp.async ring, ONE __syncthreads per chunk.
// EPI 0: bias, fp32 store. EPI 1: bias+relu -> fp16 hi/lo. EPI 2: C += acc+bias.
// ---------------------------------------------------------------------------
#define KC   64
#define AST  72                       // padded row length (fp16 elems)
#define ARB  (AST*2)                  // 144 bytes/row
#define TILEB (128*ARB)               // 18432 B per array tile
#define STAGEB (4*TILEB)              // 73728 B per stage (Ah|Al|Wh|Wl)
#define NSTAGE 3
#define GEMM_SMEM (NSTAGE*STAGEB)     // 221184 B

__device__ __forceinline__ void gemm_issue_chunk(
    const __half* pAh, const __half* pAl,
    const __half* pWh, const __half* pWl,
    int K, int c, uint32_t dst0, int tid) {
    const __half* srcs[4] = {pAh + (size_t)c * KC, pAl + (size_t)c * KC,
                             pWh + (size_t)c * KC, pWl + (size_t)c * KC};
    #pragma unroll
    for (int arr = 0; arr < 4; arr++) {
        const __half* p = srcs[arr];
        uint32_t d0 = dst0 + arr * TILEB;
        #pragma unroll
        for (int i = 0; i < 2; i++) {
            int idx = i * 512 + tid;
            int r = idx >> 3, cc = idx & 7;
            cp_async16(d0 + r * ARB + cc * 16, p + (size_t)r * K + cc * 8);
        }
    }
    cp_commit();
}

template <int EPI>
__global__ __launch_bounds__(512, 1)
void tc_gemm(const __half* __restrict__ Ah, const __half* __restrict__ Al,
             const __half* __restrict__ Wh, const __half* __restrict__ Wl,
             const float* __restrict__ bias, float* __restrict__ C,
             __half* __restrict__ Oh, __half* __restrict__ Ol,
             int Nn, int K) {
    extern __shared__ __align__(16) char smem[];
    __shared__ float sbias[128];
    uint32_t sb = smem_u32(smem);
    int tid = threadIdx.x;
    int bm = blockIdx.y * 128;
    int bn = blockIdx.x * 128;

    if (tid < 128) sbias[tid] = bias[bn + tid];

    const __half* pAh = Ah + (size_t)bm * K;
    const __half* pAl = Al + (size_t)bm * K;
    const __half* pWh = Wh + (size_t)bn * K;
    const __half* pWl = Wl + (size_t)bn * K;

    int l = tid & 31, warp = tid >> 5;
    int wm = warp >> 2, wn = warp & 3;       // 4x4 warps, warp tile 32x32

    float acc[2][4][4];                       // main term, fp32 acc
    uint32_t cor[2][4][2];                    // corrections, fp16 acc (half2 pairs)
    #pragma unroll
    for (int i = 0; i < 2; i++)
        #pragma unroll
        for (int j = 0; j < 4; j++) {
            #pragma unroll
            for (int k = 0; k < 4; k++) acc[i][j][k] = 0.0f;
            cor[i][j][0] = 0u; cor[i][j][1] = 0u;
        }

    // ldmatrix lane addressing
    int arow  = wm * 32 + (l & 15);
    int acolb = (l >> 4) * 16;
    int brow  = wn * 32 + ((l >> 4) & 1) * 8 + (l & 7);
    int bcolb = ((l >> 3) & 1) * 16;

    int NC = K / KC;

    gemm_issue_chunk(pAh, pAl, pWh, pWl, K, 0, sb, tid);
    gemm_issue_chunk(pAh, pAl, pWh, pWl, K, 1, sb + STAGEB, tid);

    int stage = 0;
    for (int c = 0; c < NC; c++) {
        if (c + 1 < NC) cp_wait<1>(); else cp_wait<0>();
        __syncthreads();

        uint32_t sA  = sb + stage * STAGEB;
        uint32_t sAl = sA + TILEB;
        uint32_t sW  = sA + 2 * TILEB;
        uint32_t sWl = sA + 3 * TILEB;

        #pragma unroll
        for (int ks = 0; ks < KC / 16; ks++) {
            uint32_t ah[2][4], al4[2][4], wh[2][4], wl4[2][4];
            #pragma unroll
            for (int i = 0; i < 2; i++) {
                uint32_t off = (uint32_t)(arow + i * 16) * ARB + ks * 32 + acolb;
                ldsm_x4(ah[i],  sA  + off);
                ldsm_x4(al4[i], sAl + off);
            }
            #pragma unroll
            for (int jp = 0; jp < 2; jp++) {
                uint32_t off = (uint32_t)(brow + jp * 16) * ARB + ks * 32 + bcolb;
                ldsm_x4(wh[jp],  sW  + off);
                ldsm_x4(wl4[jp], sWl + off);
            }
            #pragma unroll
            for (int i = 0; i < 2; i++)
                #pragma unroll
                for (int j = 0; j < 4; j++) {
                    const uint32_t* bh = &wh[j >> 1][(j & 1) * 2];
                    const uint32_t* bl = &wl4[j >> 1][(j & 1) * 2];
                    mma_f32acc(acc[i][j], ah[i], bh);      // main (fp32 acc)
                    mma_f16acc(cor[i][j], ah[i], bl);      // corr  (fp16 acc)
                    mma_f16acc(cor[i][j], al4[i], bh);     // corr  (fp16 acc)
                }
        }

        if (c + 2 < NC) {
            int ns = stage + 2; if (ns >= NSTAGE) ns -= NSTAGE;
            gemm_issue_chunk(pAh, pAl, pWh, pWl, K, c + 2, sb + ns * STAGEB, tid);
        }
        if (++stage >= NSTAGE) stage = 0;
    }

    // epilogue: main fragment (c0,c1)->(row,col..col+1); (c2,c3)->(row+8,..)
    // correction reg0 = half2(c0,c1), reg1 = half2(c2,c3) with same mapping.
    int r0 = bm + wm * 32 + (l >> 2);
    int cb = wn * 32 + 2 * (l & 3);
    #pragma unroll
    for (int i = 0; i < 2; i++) {
        #pragma unroll
        for (int j = 0; j < 4; j++) {
            int col = cb + j * 8;
            float b0 = sbias[col], b1 = sbias[col + 1];
            #pragma unroll
            for (int half = 0; half < 2; half++) {
                __half2 ch = *(__half2*)&cor[i][j][half];
                float2 cf = __half22float2(ch);
                int m = r0 + i * 16 + half * 8;
                float v0 = acc[i][j][2 * half]     + cf.x + b0;
                float v1 = acc[i][j][2 * half + 1] + cf.y + b1;
                size_t idx = (size_t)m * Nn + bn + col;
                if (EPI == 0) {
                    float2 s = {v0, v1};
                    *(float2*)(C + idx) = s;
                } else if (EPI == 2) {
                    float2 old = *(const float2*)(C + idx);
                    float2 s = {v0 + old.x, v1 + old.y};
                    *(float2*)(C + idx) = s;
                } else {  // EPI 1: relu -> fp16 hi/lo split
                    v0 = fmaxf(v0, 0.0f);
                    v1 = fmaxf(v1, 0.0f);
                    __half h0 = __float2half_rn(v0);
                    __half h1 = __float2half_rn(v1);
                    __half2 h2 = __halves2half2(h0, h1);
                    __half2 l2 = __halves2half2(
                        __float2half_rn(v0 - __half2float(h0)),
                        __float2half_rn(v1 - __half2float(h1)));
                    *(__half2*)(Oh + idx) = h2;
                    *(__half2*)(Ol + idx) = l2;
                }
            }
        }
    }
}

// ---------------------------------------------------------------------------
// Fused attention: one CTA per (b,h), 512 threads, K/V resident in SMEM.
// Reads qkv fp32, writes attention output as fp16 hi/lo split.
// ---------------------------------------------------------------------------
#define KST 68
#define ATTN_SMEM ((SEQ*KST + SEQ*HD + 16*4*SEQ) * 4)

__global__ __launch_bounds__(512, 1) void attn_kernel(const float* __restrict__ qkv,
                                                      const float* __restrict__ mask,
                                                      __half* __restrict__ oh,
                                                      __half* __restrict__ ol) {
    extern __shared__ __align__(16) float sm[];
    float* Ks = sm;
    float* Vs = Ks + SEQ * KST;
    float* Ps = Vs + SEQ * HD;

    int bh = blockIdx.x;
    int b  = bh >> 4;
    int h  = bh & 15;
    int tid = threadIdx.x;

    for (int idx = tid; idx < SEQ * 16; idx += 512) {
        int s = idx >> 4;
        int c = (idx & 15) << 2;
        size_t base = ((size_t)s * BATCH + b) * (3 * PD) + (size_t)h * HD + c;
        float4 k4 = *(const float4*)(qkv + base + PD);
        float4 v4 = *(const float4*)(qkv + base + 2 * PD);
        *(float4*)(Ks + s * KST + c) = k4;
        *(float4*)(Vs + s * HD + c) = v4;
    }
    __syncthreads();

    int warp = tid >> 5, lane = tid & 31;
    float* Pw = Ps + warp * 4 * SEQ;
    const size_t qtstep = (size_t)BATCH * 3 * PD;

    for (int it = 0; it < 4; it++) {
        int t0 = warp * 16 + it * 4;
        const float* qp0 = qkv + ((size_t)t0 * BATCH + b) * (3 * PD) + (size_t)h * HD;

        unsigned long long sc2[4][8];
        #pragma unroll
        for (int q = 0; q < 4; q++)
            #pragma unroll
            for (int j = 0; j < 8; j++) sc2[q][j] = 0ull;

        #pragma unroll 2
        for (int d4 = 0; d4 < 16; d4++) {
            const float* qb = qp0 + 4 * d4;
            ulonglong2 aq0 = *(const ulonglong2*)(qb);
            ulonglong2 aq1 = *(const ulonglong2*)(qb + qtstep);
            ulonglong2 aq2 = *(const ulonglong2*)(qb + 2 * qtstep);
            ulonglong2 aq3 = *(const ulonglong2*)(qb + 3 * qtstep);
            #pragma unroll
            for (int j = 0; j < 8; j++) {
                int s = lane + 32 * j;
                ulonglong2 k2 = *(const ulonglong2*)(Ks + s * KST + 4 * d4);
                sc2[0][j] = fma2(aq0.x, k2.x, sc2[0][j]);
                sc2[0][j] = fma2(aq0.y, k2.y, sc2[0][j]);
                sc2[1][j] = fma2(aq1.x, k2.x, sc2[1][j]);
                sc2[1][j] = fma2(aq1.y, k2.y, sc2[1][j]);
                sc2[2][j] = fma2(aq2.x, k2.x, sc2[2][j]);
                sc2[2][j] = fma2(aq2.y, k2.y, sc2[2][j]);
                sc2[3][j] = fma2(aq3.x, k2.x, sc2[3][j]);
                sc2[3][j] = fma2(aq3.y, k2.y, sc2[3][j]);
            }
        }

        #pragma unroll
        for (int q = 0; q < 4; q++) {
            float pr[8];
            const float* mrow = mask + (size_t)(t0 + q) * SEQ;
            #pragma unroll
            for (int j = 0; j < 8; j++) {
                float lo, hi;
                unpack2(sc2[q][j], lo, hi);
                pr[j] = (lo + hi) * 0.125f + mrow[lane + 32 * j];
            }
            float mx = pr[0];
            #pragma unroll
            for (int j = 1; j < 8; j++) mx = fmaxf(mx, pr[j]);
            #pragma unroll
            for (int o = 16; o; o >>= 1) mx = fmaxf(mx, __shfl_xor_sync(0xffffffffu, mx, o));
            float sum = 0.0f;
            #pragma unroll
            for (int j = 0; j < 8; j++) { pr[j] = __expf(pr[j] - mx); sum += pr[j]; }
            #pragma unroll
            for (int o = 16; o; o >>= 1) sum += __shfl_xor_sync(0xffffffffu, sum, o);
            float inv = 1.0f / sum;
            #pragma unroll
            for (int j = 0; j < 8; j++) Pw[q * SEQ + lane + 32 * j] = pr[j] * inv;
        }
        __syncwarp();

        float2 acc0 = {0, 0}, acc1 = {0, 0}, acc2v = {0, 0}, acc3 = {0, 0};
        const float* vcol = Vs + 2 * lane;
        for (int s = 0; s < SEQ; s++) {
            float2 v2 = *(const float2*)(vcol + s * HD);
            float p0 = Pw[s];
            float p1 = Pw[SEQ + s];
            float p2 = Pw[2 * SEQ + s];
            float p3 = Pw[3 * SEQ + s];
            acc0.x = fmaf(p0, v2.x, acc0.x); acc0.y = fmaf(p0, v2.y, acc0.y);
            acc1.x = fmaf(p1, v2.x, acc1.x); acc1.y = fmaf(p1, v2.y, acc1.y);
            acc2v.x = fmaf(p2, v2.x, acc2v.x); acc2v.y = fmaf(p2, v2.y, acc2v.y);
            acc3.x = fmaf(p3, v2.x, acc3.x); acc3.y = fmaf(p3, v2.y, acc3.y);
        }
        size_t obase = ((size_t)t0 * BATCH + b) * PD + (size_t)h * HD + 2 * lane;
        size_t ostep = (size_t)BATCH * PD;
        float2 accs[4] = {acc0, acc1, acc2v, acc3};
        #pragma unroll
        for (int q = 0; q < 4; q++) {
            size_t oidx = obase + q * ostep;
            __half hx = __float2half_rn(accs[q].x);
            __half hy = __float2half_rn(accs[q].y);
            __half2 h2 = __halves2half2(hx, hy);
            __half2 l2 = __halves2half2(
                __float2half_rn(accs[q].x - __half2float(hx)),
                __float2half_rn(accs[q].y - __half2float(hy)));
            *(__half2*)(oh + oidx) = h2;
            *(__half2*)(ol + oidx) = l2;
        }
        __syncwarp();
    }
}

// ---------------------------------------------------------------------------
// Host orchestration
// ---------------------------------------------------------------------------
extern "C" void kernel_launch(void* const* d_in, const int* in_sizes, int n_in,
                              void* d_out, int out_size) {
    const float* src  = (const float*)d_in[0];
    const float* mask = (const float*)d_in[1];
    const float* Wqkv = (const float*)d_in[2];
    const float* bqkv = (const float*)d_in[3];
    const float* Wo   = (const float*)d_in[4];
    const float* bo   = (const float*)d_in[5];
    const float* ln1g = (const float*)d_in[6];
    const float* ln1b = (const float*)d_in[7];
    const float* ln2g = (const float*)d_in[8];
    const float* ln2b = (const float*)d_in[9];
    const float* W1   = (const float*)d_in[10];
    const float* b1   = (const float*)d_in[11];
    const float* W2   = (const float*)d_in[12];
    const float* b2   = (const float*)d_in[13];
    const float* lnfg = (const float*)d_in[14];
    const float* lnfb = (const float*)d_in[15];

    float* x = (float*)d_out;

    void *pqkv, *pah, *pal, *pffh, *pffl, *pwh, *pwl;
    cudaGetSymbolAddress(&pqkv, g_qkv);
    cudaGetSymbolAddress(&pah, g_ah);
    cudaGetSymbolAddress(&pal, g_al);
    cudaGetSymbolAddress(&pffh, g_ffh);
    cudaGetSymbolAddress(&pffl, g_ffl);
    cudaGetSymbolAddress(&pwh, g_wh);
    cudaGetSymbolAddress(&pwl, g_wl);
    float* qk = (float*)pqkv;
    __half* ah  = (__half*)pah;
    __half* al  = (__half*)pal;
    __half* ffh = (__half*)pffh;
    __half* ffl = (__half*)pffl;
    __half* wh  = (__half*)pwh;
    __half* wl  = (__half*)pwl;

    cudaFuncSetAttribute(attn_kernel, cudaFuncAttributeMaxDynamicSharedMemorySize,
                         ATTN_SMEM);
    cudaFuncSetAttribute(tc_gemm<0>, cudaFuncAttributeMaxDynamicSharedMemorySize,
                         GEMM_SMEM);
    cudaFuncSetAttribute(tc_gemm<1>, cudaFuncAttributeMaxDynamicSharedMemorySize,
                         GEMM_SMEM);
    cudaFuncSetAttribute(tc_gemm<2>, cudaFuncAttributeMaxDynamicSharedMemorySize,
                         GEMM_SMEM);

    // x = src
    copy_kernel<<<ROWS * NF / (256 * 4), 256>>>(src, x);

    dim3 gQKV(3 * PD / 128, ROWS / 128);   // (24, 64)
    dim3 gWO(NF / 128, ROWS / 128);        // (8, 64)
    dim3 gW1(FF / 128, ROWS / 128);        // (32, 64)
    dim3 gW2(NF / 128, ROWS / 128);        // (8, 64)

    for (int l = 0; l < LAYERS; l++) {
        const float* wqkv = Wqkv + (size_t)l * 3 * PD * NF;
        const float* bq   = bqkv + (size_t)l * 3 * PD;
        const float* wo   = Wo   + (size_t)l * NF * PD;
        const float* bo_  = bo   + (size_t)l * NF;
        const float* w1   = W1   + (size_t)l * FF * NF;
        const float* bb1  = b1   + (size_t)l * FF;
        const float* w2   = W2   + (size_t)l * NF * FF;
        const float* bb2  = b2   + (size_t)l * NF;

        // --- attention block ---
        ln_kernel<1><<<ROWS, 256>>>(x, ln1g + (size_t)l * NF, ln1b + (size_t)l * NF,
                                    nullptr, ah, al);
        convw_kernel<<<(3 * PD * NF) / 1024, 256>>>(wqkv, wh, wl);
        tc_gemm<0><<<gQKV, 512, GEMM_SMEM>>>(ah, al, wh, wl, bq, qk,
                                             nullptr, nullptr, 3 * PD, NF);
        attn_kernel<<<BATCH * NH, 512, ATTN_SMEM>>>(qk, mask, ah, al);
        convw_kernel<<<(NF * PD) / 1024, 256>>>(wo, wh, wl);
        tc_gemm<2><<<gWO, 512, GEMM_SMEM>>>(ah, al, wh, wl, bo_, x,
                                            nullptr, nullptr, NF, PD);

        // --- FFN block ---
        ln_kernel<1><<<ROWS, 256>>>(x, ln2g + (size_t)l * NF, ln2b + (size_t)l * NF,
                                    nullptr, ah, al);
        convw_kernel<<<(FF * NF) / 1024, 256>>>(w1, wh, wl);
        tc_gemm<1><<<gW1, 512, GEMM_SMEM>>>(ah, al, wh, wl, bb1, nullptr,
                                            ffh, ffl, FF, NF);
        convw_kernel<<<(NF * FF) / 1024, 256>>>(w2, wh, wl);
        tc_gemm<2><<<gW2, 512, GEMM_SMEM>>>(ffh, ffl, wh, wl, bb2, x,
                                            nullptr, nullptr, NF, FF);
    }

    // final LN (fp32, in-place on d_out)
    ln_kernel<0><<<ROWS, 256>>>(x, lnfg, lnfb, x, nullptr, nullptr);
}